// round 6
// baseline (speedup 1.0000x reference)
#include <cuda_runtime.h>
#include <cuda_bf16.h>
#include <cstdint>

#define B   64
#define H   480
#define W   640
#define PH  64
#define PW  512
#define FS  15
#define NF  7
#define RAD 7

#define K_TOT   (PH*PW)          // 32768
#define N_ROWS  (B*NF)           // 448

#define CODES_OFF 0
#define GRAM_OFF  (B*NF*PH*PW)                // 14680064
#define POLAR_OFF (GRAM_OFF + N_ROWS*N_ROWS)  // 14880768

// ---- gram tiling ----
#define GT       4
#define GPAIRS   10
#define GKSPLIT  32
#define GKCHUNK  (K_TOT/GKSPLIT)    // 1024
#define KB       32
#define KITERS   (GKCHUNK/KB)       // 32

#define TSTRIDE  40                 // bf16 per smem row (80B)
#define TILE_BY  (128*TSTRIDE*2)    // 10240 B
#define STAGE_BY (4*TILE_BY)        // 40960 B
#define NSTAGE   4
#define GSMEM    (NSTAGE*STAGE_BY)  // 163840 B

// ---- conv (implicit GEMM) ----
#define YSTRIP  16
#define AROWS   30                  // YSTRIP + 14
#define ACOLS   536                 // 528 used + pad
#define AFBYTES (AROWS*ACOLS*4)     // 64320
#define BFELEMS (FS*16*8)           // 1920
#define BFBYTES (BFELEMS*4)         // 7680
#define SSTR    68                  // staging stride (float4-aligned, conflict-free)
#define STG_F   (8*SSTR)            // 544 floats per warp
#define OFF_BH  AFBYTES
#define OFF_BL  (AFBYTES + BFBYTES)
#define OFF_STG (AFBYTES + 2*BFBYTES)
#define CONV_SMEM (OFF_STG + 8*STG_F*4)   // 97088 B

// scratch (device-code references ONLY — host-side symbol use is a silent
// ATS write to host BSS on GB300)
__device__ __nv_bfloat16 g_hi[(size_t)N_ROWS * K_TOT];
__device__ __nv_bfloat16 g_lo[(size_t)N_ROWS * K_TOT];
__device__ float g_gpart[GPAIRS][GKSPLIT][128*128];

// ===========================================================================
// helpers
// ===========================================================================
__device__ __forceinline__ uint32_t smem_u32(const void* p) {
    uint32_t a;
    asm("{ .reg .u64 t; cvta.to.shared.u64 t, %1; cvt.u32.u64 %0, t; }" : "=r"(a) : "l"(p));
    return a;
}

__device__ __forceinline__ void cp16(uint32_t dst, const void* src) {
    asm volatile("cp.async.ca.shared.global [%0], [%1], 16;" :: "r"(dst), "l"(src));
}
__device__ __forceinline__ void cp16z(uint32_t dst, const void* src) {
    asm volatile("cp.async.ca.shared.global [%0], [%1], 16, 0;" :: "r"(dst), "l"(src));
}
__device__ __forceinline__ void cp_commit() { asm volatile("cp.async.commit_group;" ::: "memory"); }
__device__ __forceinline__ void cp_wait2()  { asm volatile("cp.async.wait_group 2;" ::: "memory"); }

__device__ __forceinline__ void ldm_x4(uint32_t* r, uint32_t addr) {
    asm volatile("ldmatrix.sync.aligned.m8n8.x4.shared.b16 {%0,%1,%2,%3}, [%4];"
        : "=r"(r[0]), "=r"(r[1]), "=r"(r[2]), "=r"(r[3]) : "r"(addr));
}
__device__ __forceinline__ void mma_bf16(float* c, const uint32_t* a, uint32_t b0, uint32_t b1) {
    asm volatile("mma.sync.aligned.m16n8k16.row.col.f32.bf16.bf16.f32 "
        "{%0,%1,%2,%3}, {%4,%5,%6,%7}, {%8,%9}, {%0,%1,%2,%3};"
        : "+f"(c[0]), "+f"(c[1]), "+f"(c[2]), "+f"(c[3])
        : "r"(a[0]), "r"(a[1]), "r"(a[2]), "r"(a[3]), "r"(b0), "r"(b1));
}
__device__ __forceinline__ void mma_tf32(float* c, const uint32_t* a, uint32_t b0, uint32_t b1) {
    asm volatile("mma.sync.aligned.m16n8k8.row.col.f32.tf32.tf32.f32 "
        "{%0,%1,%2,%3}, {%4,%5,%6,%7}, {%8,%9}, {%0,%1,%2,%3};"
        : "+f"(c[0]), "+f"(c[1]), "+f"(c[2]), "+f"(c[3])
        : "r"(a[0]), "r"(a[1]), "r"(a[2]), "r"(a[3]), "r"(b0), "r"(b1));
}
__device__ __forceinline__ uint32_t tf32_hi(float v) {
    uint32_t h;
    asm("cvt.rna.tf32.f32 %0, %1;" : "=r"(h) : "f"(v));
    return h;
}

// ===========================================================================
// Kernel 1: polar bilinear resample
// ===========================================================================
__global__ void polar_kernel(const float* __restrict__ img,
                             const float* __restrict__ pupil,
                             const float* __restrict__ iris,
                             float* __restrict__ polar) {
    int idx = blockIdx.x * blockDim.x + threadIdx.x;
    if (idx >= B * PH * PW) return;
    int col = idx % PW;
    int row = (idx / PW) % PH;
    int b   = idx / (PH * PW);

    float theta = 6.283185307179586f * (float)(col + 1) * (1.0f / (float)PW);
    float ct = cosf(theta), st = sinf(theta);

    float pcx = pupil[b*3+0], pcy = pupil[b*3+1], pr = pupil[b*3+2];
    float icx = iris [b*3+0], icy = iris [b*3+1], ir = iris [b*3+2];

    float px = pcx + pr * ct;
    float py = pcy + pr * st;
    float ix = icx + ir * ct;
    float iy = icy + ir * st;

    float rad = (float)row / (float)(PH - 1);
    float xg = (1.0f - rad) * px + rad * ix;
    float yg = (1.0f - rad) * py + rad * iy;

    float x = fminf(fmaxf(xg, 0.0f), (float)(W - 1));
    float y = fminf(fmaxf(yg, 0.0f), (float)(H - 1));

    float xn = x / (float)(W - 1) * 2.0f - 1.0f;
    float yn = y / (float)(H - 1) * 2.0f - 1.0f;
    float gx = ((xn + 1.0f) * 0.5f * (float)W - 0.5f) / (float)(W - 1) * 2.0f - 1.0f;
    float gy = ((yn + 1.0f) * 0.5f * (float)H - 0.5f) / (float)(H - 1) * 2.0f - 1.0f;
    float sx = ((gx + 1.0f) * (float)W - 1.0f) * 0.5f;
    float sy = ((gy + 1.0f) * (float)H - 1.0f) * 0.5f;

    float x0f = floorf(sx), y0f = floorf(sy);
    float wx = sx - x0f, wy = sy - y0f;
    int x0 = (int)x0f, y0 = (int)y0f;

    const float* im = img + (size_t)b * H * W;

    float v00 = 0.f, v01 = 0.f, v10 = 0.f, v11 = 0.f;
    bool xv0 = (x0 >= 0) && (x0 < W);
    bool xv1 = (x0+1 >= 0) && (x0+1 < W);
    bool yv0 = (y0 >= 0) && (y0 < H);
    bool yv1 = (y0+1 >= 0) && (y0+1 < H);
    int x0c = min(max(x0, 0), W-1), x1c = min(max(x0+1, 0), W-1);
    int y0c = min(max(y0, 0), H-1), y1c = min(max(y0+1, 0), H-1);
    if (xv0 && yv0) v00 = im[y0c*W + x0c] * 255.0f;
    if (xv1 && yv0) v01 = im[y0c*W + x1c] * 255.0f;
    if (xv0 && yv1) v10 = im[y1c*W + x0c] * 255.0f;
    if (xv1 && yv1) v11 = im[y1c*W + x1c] * 255.0f;

    float v = v00*(1.0f-wx)*(1.0f-wy) + v01*wx*(1.0f-wy)
            + v10*(1.0f-wx)*wy        + v11*wx*wy;
    polar[idx] = v;
}

// ===========================================================================
// Kernel 2: conv as implicit GEMM on tf32 tensor cores (hi/lo 3-term split).
// Block: (batch, 16-row y-strip), 256 thr / 8 warps. Warp-tile: 1 y row,
// 64 x, 8 filters (n=7 used). K = 15 filter rows x 16 taps (k15 zero-pad).
// Hankel A-operand: per lane 18 scalar LDS.32 cover all frags of one i-row.
// ===========================================================================
__global__ __launch_bounds__(256, 2)
void conv_mma_kernel(const float* __restrict__ polar,
                     const float* __restrict__ filt,
                     float* __restrict__ codes) {
    extern __shared__ char csm[];
    float* aF  = (float*)csm;                 // [AROWS][ACOLS] fp32 polar tile
    float* bH  = (float*)(csm + OFF_BH);      // [15][16][8] tf32-hi filter
    float* bL  = (float*)(csm + OFF_BL);      // [15][16][8] residual
    float* stg = (float*)(csm + OFF_STG);     // per-warp [8][SSTR] staging

    int b  = blockIdx.x;
    int y0 = blockIdx.y * YSTRIP;
    int tid = threadIdx.x, wid = tid >> 5, lane = tid & 31;

    // filter prep: B[n=o][k=j] = filt[(i*15+j)*7 + (6-o)], pads zero
    for (int e = tid; e < BFELEMS; e += 256) {
        int i = e >> 7;
        int k = (e >> 3) & 15;
        int n = e & 7;
        float w = (n < NF && k < FS) ? filt[(i*FS + k)*NF + (6 - n)] : 0.f;
        uint32_t hb = tf32_hi(w);
        bH[e] = __uint_as_float(hb);
        bL[e] = w - __uint_as_float(hb);
    }
    // A tile: rows y0-7..y0+22 (wrap), cols x=-7..520 (wrap)
    const float* pb = polar + (size_t)b * PH * PW;
    for (int e = tid; e < AROWS * 528; e += 256) {
        int r = e / 528, c = e % 528;
        int gy = (y0 - RAD + r) & (PH - 1);
        int gx = (c - RAD) & (PW - 1);
        aF[r * ACOLS + c] = pb[gy * PW + gx];
    }
    __syncthreads();

    int ebase = (lane >> 2) + (lane & 3);   // per-lane Hankel base
    int bn = lane >> 2;                     // B: n = lane/4
    int bk = lane & 3;                      // B: k = lane%4
    float* sw = stg + wid * STG_F;

    for (int t = 0; t < 16; t++) {
        int wt = wid * 16 + t;
        int yl = wt >> 3;              // 0..15
        int x0 = (wt & 7) << 6;        // 0..448

        float acc[4][4];
        #pragma unroll
        for (int mf = 0; mf < 4; mf++)
            #pragma unroll
            for (int q = 0; q < 4; q++) acc[mf][q] = 0.f;

        #pragma unroll 1
        for (int i = 0; i < FS; i++) {
            const float* ar = &aF[(yl + i) * ACOLS + x0 + ebase];
            uint32_t vh[18], vl[18];
            #pragma unroll
            for (int s = 0; s < 18; s++) {
                float v = ar[4*s];
                uint32_t hb = tf32_hi(v);
                vh[s] = hb;
                vl[s] = __float_as_uint(v - __uint_as_float(hb));
            }
            const float* bhr = &bH[(i*16 + bk)*8 + bn];
            const float* blr = &bL[(i*16 + bk)*8 + bn];
            #pragma unroll
            for (int ks = 0; ks < 2; ks++) {
                uint32_t bh0 = __float_as_uint(bhr[ks*64]);       // k = ks*8+bk
                uint32_t bh1 = __float_as_uint(bhr[ks*64 + 32]);  // k + 4
                uint32_t bl0 = __float_as_uint(blr[ks*64]);
                uint32_t bl1 = __float_as_uint(blr[ks*64 + 32]);
                #pragma unroll
                for (int mf = 0; mf < 4; mf++) {
                    int s = 4*mf + 2*ks;
                    uint32_t ah[4] = {vh[s], vh[s+2], vh[s+1], vh[s+3]};
                    uint32_t al[4] = {vl[s], vl[s+2], vl[s+1], vl[s+3]};
                    mma_tf32(acc[mf], ah, bh0, bh1);
                    mma_tf32(acc[mf], ah, bl0, bl1);
                    mma_tf32(acc[mf], al, bh0, bh1);
                }
            }
        }

        // epilogue: transpose via staging smem, then vectorized stores
        __syncwarp();
        int so = (lane & 3) * 2;       // n (filter) base
        int sx = lane >> 2;            // m (x) base
        #pragma unroll
        for (int mf = 0; mf < 4; mf++) {
            int xb = mf*16 + sx;
            sw[so*SSTR + xb]     = acc[mf][0];
            sw[so*SSTR + xb + 8] = acc[mf][2];
            if (so < 6) {
                sw[(so+1)*SSTR + xb]     = acc[mf][1];
                sw[(so+1)*SSTR + xb + 8] = acc[mf][3];
            }
        }
        __syncwarp();
        int y = y0 + yl;
        for (int e = lane; e < 112; e += 32) {
            int o  = e >> 4;
            int xq = (e & 15) << 2;
            float4 v = *(float4*)&sw[o*SSTR + xq];
            size_t off = (((size_t)(b*NF + o))*PH + y)*PW + x0 + xq;
            *(float4*)&codes[off] = v;

            __nv_bfloat16 h0 = __float2bfloat16(v.x);
            __nv_bfloat16 h1 = __float2bfloat16(v.y);
            __nv_bfloat16 h2 = __float2bfloat16(v.z);
            __nv_bfloat16 h3 = __float2bfloat16(v.w);
            __nv_bfloat16 l0 = __float2bfloat16(v.x - __bfloat162float(h0));
            __nv_bfloat16 l1 = __float2bfloat16(v.y - __bfloat162float(h1));
            __nv_bfloat16 l2 = __float2bfloat16(v.z - __bfloat162float(h2));
            __nv_bfloat16 l3 = __float2bfloat16(v.w - __bfloat162float(h3));
            uint2 oh, ol;
            oh.x = ((uint32_t)__bfloat16_as_ushort(h1) << 16) | __bfloat16_as_ushort(h0);
            oh.y = ((uint32_t)__bfloat16_as_ushort(h3) << 16) | __bfloat16_as_ushort(h2);
            ol.x = ((uint32_t)__bfloat16_as_ushort(l1) << 16) | __bfloat16_as_ushort(l0);
            ol.y = ((uint32_t)__bfloat16_as_ushort(l3) << 16) | __bfloat16_as_ushort(l2);
            *(uint2*)&g_hi[off] = oh;
            *(uint2*)&g_lo[off] = ol;
        }
        __syncwarp();
    }
}

// ===========================================================================
// Kernel 3: gram via mma.sync bf16 (hi/lo, 3 terms), 16 warps, 4-stage ring.
// ===========================================================================
__device__ __forceinline__ void gram_load_stage(uint32_t sbase, int stage, int it,
                                                int ti, int tj, int ksp, int tid, int nm) {
    uint32_t st = sbase + stage * STAGE_BY;
    size_t kbyte = ((size_t)ksp * GKCHUNK + (size_t)it * KB) * 2;
    int row = tid >> 2, k8 = tid & 3;
    uint32_t doff = (uint32_t)(row * (TSTRIDE*2) + k8 * 16);
    #pragma unroll
    for (int m = 0; m < 4; m++) {
        if (m >= nm) break;
        int grow = ((m < 2) ? ti : tj) * 128 + row;
        const char* matbase = (m & 1) ? (const char*)g_lo : (const char*)g_hi;
        uint32_t dst = st + m * TILE_BY + doff;
        const char* src = matbase + (size_t)min(grow, N_ROWS-1) * (K_TOT*2) + kbyte + k8 * 16;
        if (grow < N_ROWS) cp16(dst, src);
        else               cp16z(dst, src);
    }
}

__global__ __launch_bounds__(512, 1)
void gram_mma_kernel() {
    extern __shared__ char dsm[];
    uint32_t sbase = smem_u32(dsm);

    int pair = blockIdx.x;
    int ksp  = blockIdx.y;
    int ti = 0, rem = pair, cnt = GT;
    while (rem >= cnt) { rem -= cnt; ti++; cnt--; }
    int tj = ti + rem;
    bool diag = (ti == tj);
    int nm = diag ? 2 : 4;

    int tid  = threadIdx.x;
    int wid  = tid >> 5, lane = tid & 31;
    int warp_m = wid & 3;
    int warp_n = wid >> 2;

    float acc[2][4][4];
    #pragma unroll
    for (int mi = 0; mi < 2; mi++)
        #pragma unroll
        for (int ni = 0; ni < 4; ni++)
            #pragma unroll
            for (int q = 0; q < 4; q++) acc[mi][ni][q] = 0.f;

    uint32_t a_off = (uint32_t)((warp_m*32 + (lane & 15)) * (TSTRIDE*2) + ((lane >> 4) & 1) * 16);
    uint32_t b_off = (uint32_t)((warp_n*32 + (lane & 15)) * (TSTRIDE*2) + ((lane >> 4) & 1) * 16);

    #pragma unroll
    for (int p = 0; p < 3; p++) {
        gram_load_stage(sbase, p, p, ti, tj, ksp, tid, nm);
        cp_commit();
    }

    for (int it = 0; it < KITERS; it++) {
        cp_wait2();
        __syncthreads();

        uint32_t st  = sbase + (it & 3) * STAGE_BY;
        uint32_t aHi = st;
        uint32_t aLo = st + TILE_BY;
        uint32_t bHi = diag ? st           : st + 2*TILE_BY;
        uint32_t bLo = diag ? st + TILE_BY : st + 3*TILE_BY;

        #pragma unroll
        for (int k16 = 0; k16 < 2; k16++) {
            uint32_t kadd = (uint32_t)(k16 * 32);
            uint32_t ahi[2][4], alo[2][4];
            #pragma unroll
            for (int mi = 0; mi < 2; mi++) {
                ldm_x4(ahi[mi], aHi + a_off + kadd + mi*16*(TSTRIDE*2));
                ldm_x4(alo[mi], aLo + a_off + kadd + mi*16*(TSTRIDE*2));
            }
            uint32_t bhiR[2][4], bloR[2][4];
            #pragma unroll
            for (int n2 = 0; n2 < 2; n2++) {
                ldm_x4(bhiR[n2], bHi + b_off + kadd + n2*16*(TSTRIDE*2));
                ldm_x4(bloR[n2], bLo + b_off + kadd + n2*16*(TSTRIDE*2));
            }
            #pragma unroll
            for (int mi = 0; mi < 2; mi++)
                #pragma unroll
                for (int ni = 0; ni < 4; ni++) {
                    int n2 = ni >> 1, sel = ni & 1;
                    uint32_t bh0 = bhiR[n2][sel], bh1 = bhiR[n2][sel+2];
                    uint32_t bl0 = bloR[n2][sel], bl1 = bloR[n2][sel+2];
                    mma_bf16(acc[mi][ni], ahi[mi], bh0, bh1);
                    mma_bf16(acc[mi][ni], ahi[mi], bl0, bl1);
                    mma_bf16(acc[mi][ni], alo[mi], bh0, bh1);
                }
        }

        int nx = it + 3;
        if (nx < KITERS) gram_load_stage(sbase, nx & 3, nx, ti, tj, ksp, tid, nm);
        cp_commit();
    }

    float* dst = &g_gpart[pair][ksp][0];
    int r0 = warp_m * 32;
    int c0 = warp_n * 32;
    #pragma unroll
    for (int mi = 0; mi < 2; mi++) {
        #pragma unroll
        for (int ni = 0; ni < 4; ni++) {
            int row = r0 + mi*16 + (lane >> 2);
            int col = c0 + ni*8 + (lane & 3) * 2;
            *(float2*)&dst[row * 128 + col]       = make_float2(acc[mi][ni][0], acc[mi][ni][1]);
            *(float2*)&dst[(row + 8) * 128 + col] = make_float2(acc[mi][ni][2], acc[mi][ni][3]);
        }
    }
}

// ===========================================================================
// Kernel 4: reduce K-splits, scale, symmetric write
// ===========================================================================
__global__ void gram_reduce_kernel(float* __restrict__ gram) {
    int idx = blockIdx.x * blockDim.x + threadIdx.x;
    if (idx >= GPAIRS * 128 * 128) return;
    int pair = idx >> 14;
    int e    = idx & 16383;
    int ii = e >> 7, jj = e & 127;

    int ti = 0, rem = pair, cnt = GT;
    while (rem >= cnt) { rem -= cnt; ti++; cnt--; }
    int tj = ti + rem;

    int gi = ti * 128 + ii;
    int gj = tj * 128 + jj;
    if (gi >= N_ROWS || gj >= N_ROWS) return;

    float s = 0.f;
    #pragma unroll
    for (int k = 0; k < GKSPLIT; k++) s += g_gpart[pair][k][e];
    s *= (1.0f / 14680064.0f);

    gram[gi * N_ROWS + gj] = s;
    gram[gj * N_ROWS + gi] = s;
}

// ===========================================================================
extern "C" void kernel_launch(void* const* d_in, const int* in_sizes, int n_in,
                              void* d_out, int out_size) {
    const float* image = (const float*)d_in[0];
    const float* pupil = (const float*)d_in[1];
    const float* iris  = (const float*)d_in[2];
    const float* filt  = (const float*)d_in[3];

    float* out   = (float*)d_out;
    float* codes = out + CODES_OFF;
    float* gram  = out + GRAM_OFF;
    float* polar = out + POLAR_OFF;

    cudaFuncSetAttribute(conv_mma_kernel,
                         cudaFuncAttributeMaxDynamicSharedMemorySize, CONV_SMEM);
    cudaFuncSetAttribute(gram_mma_kernel,
                         cudaFuncAttributeMaxDynamicSharedMemorySize, GSMEM);

    polar_kernel<<<(B * PH * PW) / 256, 256>>>(image, pupil, iris, polar);
    conv_mma_kernel<<<dim3(B, PH/YSTRIP), 256, CONV_SMEM>>>(polar, filt, codes);
    gram_mma_kernel<<<dim3(GPAIRS, GKSPLIT), 512, GSMEM>>>();
    gram_reduce_kernel<<<(GPAIRS * 128 * 128 + 255) / 256, 256>>>(gram);
}

// round 7
// speedup vs baseline: 1.3152x; 1.3152x over previous
#include <cuda_runtime.h>
#include <cuda_bf16.h>
#include <cstdint>

#define B   64
#define H   480
#define W   640
#define PH  64
#define PW  512
#define FS  15
#define NF  7
#define RAD 7

#define K_TOT   (PH*PW)          // 32768
#define N_ROWS  (B*NF)           // 448

#define CODES_OFF 0
#define GRAM_OFF  (B*NF*PH*PW)                // 14680064
#define POLAR_OFF (GRAM_OFF + N_ROWS*N_ROWS)  // 14880768

// ---- gram tiling ----
#define GT       4
#define GPAIRS   10
#define GKSPLIT  32
#define GKCHUNK  (K_TOT/GKSPLIT)    // 1024
#define KB       32
#define KITERS   (GKCHUNK/KB)       // 32

#define TSTRIDE  40                 // bf16 per smem row (80B)
#define TILE_BY  (128*TSTRIDE*2)    // 10240 B
#define STAGE_BY (4*TILE_BY)        // 40960 B
#define NSTAGE   4
#define GSMEM    (NSTAGE*STAGE_BY)  // 163840 B

// ---- conv (bf16 implicit GEMM) ----
#define SAB 536                     // bf16 stride per A row
#define SAU 268                     // u32 stride
#define AROWS 22                    // 8 + 14
#define ATILE_U32 (AROWS*SAU)       // 5896
#define CONV_SMEM ((4*ATILE_U32 + 2*960)*4)   // 102016 B

// scratch (device-code references ONLY — host-side symbol use is a silent
// ATS write to host BSS on GB300)
__device__ __nv_bfloat16 g_hi[(size_t)N_ROWS * K_TOT];
__device__ __nv_bfloat16 g_lo[(size_t)N_ROWS * K_TOT];
__device__ float g_gpart[GPAIRS][GKSPLIT][128*128];

// ===========================================================================
// helpers
// ===========================================================================
__device__ __forceinline__ uint32_t smem_u32(const void* p) {
    uint32_t a;
    asm("{ .reg .u64 t; cvta.to.shared.u64 t, %1; cvt.u32.u64 %0, t; }" : "=r"(a) : "l"(p));
    return a;
}

__device__ __forceinline__ void cp16(uint32_t dst, const void* src) {
    asm volatile("cp.async.ca.shared.global [%0], [%1], 16;" :: "r"(dst), "l"(src));
}
__device__ __forceinline__ void cp16z(uint32_t dst, const void* src) {
    asm volatile("cp.async.ca.shared.global [%0], [%1], 16, 0;" :: "r"(dst), "l"(src));
}
__device__ __forceinline__ void cp_commit() { asm volatile("cp.async.commit_group;" ::: "memory"); }
__device__ __forceinline__ void cp_wait2()  { asm volatile("cp.async.wait_group 2;" ::: "memory"); }

__device__ __forceinline__ void ldm_x4(uint32_t* r, uint32_t addr) {
    asm volatile("ldmatrix.sync.aligned.m8n8.x4.shared.b16 {%0,%1,%2,%3}, [%4];"
        : "=r"(r[0]), "=r"(r[1]), "=r"(r[2]), "=r"(r[3]) : "r"(addr));
}
__device__ __forceinline__ void mma_bf16(float* c, const uint32_t* a, uint32_t b0, uint32_t b1) {
    asm volatile("mma.sync.aligned.m16n8k16.row.col.f32.bf16.bf16.f32 "
        "{%0,%1,%2,%3}, {%4,%5,%6,%7}, {%8,%9}, {%0,%1,%2,%3};"
        : "+f"(c[0]), "+f"(c[1]), "+f"(c[2]), "+f"(c[3])
        : "r"(a[0]), "r"(a[1]), "r"(a[2]), "r"(a[3]), "r"(b0), "r"(b1));
}

// ===========================================================================
// Kernel 1: polar bilinear resample
// ===========================================================================
__global__ void polar_kernel(const float* __restrict__ img,
                             const float* __restrict__ pupil,
                             const float* __restrict__ iris,
                             float* __restrict__ polar) {
    int idx = blockIdx.x * blockDim.x + threadIdx.x;
    if (idx >= B * PH * PW) return;
    int col = idx % PW;
    int row = (idx / PW) % PH;
    int b   = idx / (PH * PW);

    float theta = 6.283185307179586f * (float)(col + 1) * (1.0f / (float)PW);
    float ct = cosf(theta), st = sinf(theta);

    float pcx = pupil[b*3+0], pcy = pupil[b*3+1], pr = pupil[b*3+2];
    float icx = iris [b*3+0], icy = iris [b*3+1], ir = iris [b*3+2];

    float px = pcx + pr * ct;
    float py = pcy + pr * st;
    float ix = icx + ir * ct;
    float iy = icy + ir * st;

    float rad = (float)row / (float)(PH - 1);
    float xg = (1.0f - rad) * px + rad * ix;
    float yg = (1.0f - rad) * py + rad * iy;

    float x = fminf(fmaxf(xg, 0.0f), (float)(W - 1));
    float y = fminf(fmaxf(yg, 0.0f), (float)(H - 1));

    float xn = x / (float)(W - 1) * 2.0f - 1.0f;
    float yn = y / (float)(H - 1) * 2.0f - 1.0f;
    float gx = ((xn + 1.0f) * 0.5f * (float)W - 0.5f) / (float)(W - 1) * 2.0f - 1.0f;
    float gy = ((yn + 1.0f) * 0.5f * (float)H - 0.5f) / (float)(H - 1) * 2.0f - 1.0f;
    float sx = ((gx + 1.0f) * (float)W - 1.0f) * 0.5f;
    float sy = ((gy + 1.0f) * (float)H - 1.0f) * 0.5f;

    float x0f = floorf(sx), y0f = floorf(sy);
    float wx = sx - x0f, wy = sy - y0f;
    int x0 = (int)x0f, y0 = (int)y0f;

    const float* im = img + (size_t)b * H * W;

    float v00 = 0.f, v01 = 0.f, v10 = 0.f, v11 = 0.f;
    bool xv0 = (x0 >= 0) && (x0 < W);
    bool xv1 = (x0+1 >= 0) && (x0+1 < W);
    bool yv0 = (y0 >= 0) && (y0 < H);
    bool yv1 = (y0+1 >= 0) && (y0+1 < H);
    int x0c = min(max(x0, 0), W-1), x1c = min(max(x0+1, 0), W-1);
    int y0c = min(max(y0, 0), H-1), y1c = min(max(y0+1, 0), H-1);
    if (xv0 && yv0) v00 = im[y0c*W + x0c] * 255.0f;
    if (xv1 && yv0) v01 = im[y0c*W + x1c] * 255.0f;
    if (xv0 && yv1) v10 = im[y1c*W + x0c] * 255.0f;
    if (xv1 && yv1) v11 = im[y1c*W + x1c] * 255.0f;

    float v = v00*(1.0f-wx)*(1.0f-wy) + v01*wx*(1.0f-wy)
            + v10*(1.0f-wx)*wy        + v11*wx*wy;
    polar[idx] = v;
}

// ===========================================================================
// Kernel 2: conv as bf16 implicit GEMM (hi/lo 3-term split).
// Block (b, y-strip of 8), 256 thr / 8 warps. Warp w owns y-row w, loops 8
// x-tiles of 64. A pre-split into 4 bf16 smem tiles (hi/lo x even/odd) so
// every k-pair load is an aligned LDS.32; Hankel collapse -> 9 loads cover
// all 4 m-frags x 2 k-halves.
// ===========================================================================
__global__ __launch_bounds__(256, 2)
void conv_mma_kernel(const float* __restrict__ polar,
                     const float* __restrict__ filt,
                     float* __restrict__ codes) {
    extern __shared__ uint32_t cs[];
    uint32_t* aHE = cs;
    uint32_t* aHO = cs + ATILE_U32;
    uint32_t* aLE = cs + 2*ATILE_U32;
    uint32_t* aLO = cs + 3*ATILE_U32;
    uint32_t* BsH = cs + 4*ATILE_U32;
    uint32_t* BsL = BsH + 960;

    int b  = blockIdx.x;
    int y0 = blockIdx.y * 8;
    int tid = threadIdx.x, wid = tid >> 5, lane = tid & 31;

    // B fill: BsH/BsL[i][kp][n] = bf16x2 pair (k=2kp, 2kp+1), n->o flip baked in
    for (int e = tid; e < 960; e += 256) {
        int i = e >> 6, kp = (e >> 3) & 7, n = e & 7;
        int k0 = 2*kp, k1 = 2*kp + 1;
        float w0 = (k0 < FS && n < NF) ? filt[(i*FS + k0)*NF + (6 - n)] : 0.f;
        float w1 = (k1 < FS && n < NF) ? filt[(i*FS + k1)*NF + (6 - n)] : 0.f;
        __nv_bfloat16 h0 = __float2bfloat16(w0);
        __nv_bfloat16 h1 = __float2bfloat16(w1);
        __nv_bfloat16 l0 = __float2bfloat16(w0 - __bfloat162float(h0));
        __nv_bfloat16 l1 = __float2bfloat16(w1 - __bfloat162float(h1));
        BsH[e] = ((uint32_t)__bfloat16_as_ushort(h1) << 16) | __bfloat16_as_ushort(h0);
        BsL[e] = ((uint32_t)__bfloat16_as_ushort(l1) << 16) | __bfloat16_as_ushort(l0);
    }
    // A fill: 22 rows x 529 cols (x = -7 .. 521 wrap), hi/lo + odd-shift copies
    const float* pb = polar + (size_t)b * PH * PW;
    __nv_bfloat16* aHEh = (__nv_bfloat16*)aHE;
    __nv_bfloat16* aHOh = (__nv_bfloat16*)aHO;
    __nv_bfloat16* aLEh = (__nv_bfloat16*)aLE;
    __nv_bfloat16* aLOh = (__nv_bfloat16*)aLO;
    for (int e = tid; e < AROWS * 529; e += 256) {
        int r = e / 529, c = e % 529;
        int gy = (y0 - RAD + r) & (PH - 1);
        int gx = (c - RAD) & (PW - 1);
        float v = pb[gy*PW + gx];
        __nv_bfloat16 h = __float2bfloat16(v);
        __nv_bfloat16 l = __float2bfloat16(v - __bfloat162float(h));
        aHEh[r*SAB + c] = h;
        aLEh[r*SAB + c] = l;
        if (c > 0) { aHOh[r*SAB + c - 1] = h; aLOh[r*SAB + c - 1] = l; }
    }
    __syncthreads();

    int yl = wid;                                // warp's y row (0..7)
    int pe = (lane >> 2) & 1;                    // m-parity -> even/odd tile
    int lofs = ((lane >> 2) >> 1) + (lane & 3);  // u32 offset within row
    const uint32_t* pHbase = pe ? aHO : aHE;
    const uint32_t* pLbase = pe ? aLO : aLE;
    int bi0 = (lane & 3)*8 + (lane >> 2);        // B lds index (kp, n)

    for (int xt = 0; xt < 8; xt++) {
        int x0 = xt * 64;
        int xofs = x0 >> 1;
        float acc[4][4];
        #pragma unroll
        for (int mf = 0; mf < 4; mf++)
            acc[mf][0] = acc[mf][1] = acc[mf][2] = acc[mf][3] = 0.f;

        #pragma unroll 1
        for (int i = 0; i < FS; i++) {
            const uint32_t* pH = pHbase + (yl + i)*SAU + xofs + lofs;
            const uint32_t* pL = pLbase + (yl + i)*SAU + xofs + lofs;
            uint32_t vh[9], vl[9];
            #pragma unroll
            for (int s = 0; s < 9; s++) { vh[s] = pH[4*s]; vl[s] = pL[4*s]; }
            uint32_t bh0 = BsH[i*64 + bi0];
            uint32_t bh1 = BsH[i*64 + bi0 + 32];
            uint32_t bl0 = BsL[i*64 + bi0];
            uint32_t bl1 = BsL[i*64 + bi0 + 32];
            #pragma unroll
            for (int mf = 0; mf < 4; mf++) {
                uint32_t ah[4] = {vh[2*mf], vh[2*mf+1], vh[2*mf+1], vh[2*mf+2]};
                uint32_t al[4] = {vl[2*mf], vl[2*mf+1], vl[2*mf+1], vl[2*mf+2]};
                mma_bf16(acc[mf], ah, bh0, bh1);
                mma_bf16(acc[mf], ah, bl0, bl1);
                mma_bf16(acc[mf], al, bh0, bh1);
            }
        }

        // epilogue: scattered stores (32B-coalesced groups), fused bf16 split
        int y = y0 + yl;
        int n0 = 2*(lane & 3);
        #pragma unroll
        for (int mf = 0; mf < 4; mf++) {
            int xa = x0 + mf*16 + (lane >> 2);
            #pragma unroll
            for (int q = 0; q < 4; q++) {
                int o = n0 + (q & 1);
                if (o >= NF) continue;
                int x = xa + (q >> 1)*8;
                float v = acc[mf][q];
                size_t off = (((size_t)(b*NF + o))*PH + y)*PW + x;
                codes[off] = v;
                __nv_bfloat16 hh = __float2bfloat16(v);
                g_hi[off] = hh;
                g_lo[off] = __float2bfloat16(v - __bfloat162float(hh));
            }
        }
    }
}

// ===========================================================================
// Kernel 3: gram via mma.sync bf16 (hi/lo, 3 terms), 16 warps, 4-stage ring.
// ===========================================================================
__device__ __forceinline__ void gram_load_stage(uint32_t sbase, int stage, int it,
                                                int ti, int tj, int ksp, int tid, int nm) {
    uint32_t st = sbase + stage * STAGE_BY;
    size_t kbyte = ((size_t)ksp * GKCHUNK + (size_t)it * KB) * 2;
    int row = tid >> 2, k8 = tid & 3;
    uint32_t doff = (uint32_t)(row * (TSTRIDE*2) + k8 * 16);
    #pragma unroll
    for (int m = 0; m < 4; m++) {
        if (m >= nm) break;
        int grow = ((m < 2) ? ti : tj) * 128 + row;
        const char* matbase = (m & 1) ? (const char*)g_lo : (const char*)g_hi;
        uint32_t dst = st + m * TILE_BY + doff;
        const char* src = matbase + (size_t)min(grow, N_ROWS-1) * (K_TOT*2) + kbyte + k8 * 16;
        if (grow < N_ROWS) cp16(dst, src);
        else               cp16z(dst, src);
    }
}

__global__ __launch_bounds__(512, 1)
void gram_mma_kernel() {
    extern __shared__ char dsm[];
    uint32_t sbase = smem_u32(dsm);

    int pair = blockIdx.x;
    int ksp  = blockIdx.y;
    int ti = 0, rem = pair, cnt = GT;
    while (rem >= cnt) { rem -= cnt; ti++; cnt--; }
    int tj = ti + rem;
    bool diag = (ti == tj);
    int nm = diag ? 2 : 4;

    int tid  = threadIdx.x;
    int wid  = tid >> 5, lane = tid & 31;
    int warp_m = wid & 3;
    int warp_n = wid >> 2;

    float acc[2][4][4];
    #pragma unroll
    for (int mi = 0; mi < 2; mi++)
        #pragma unroll
        for (int ni = 0; ni < 4; ni++)
            #pragma unroll
            for (int q = 0; q < 4; q++) acc[mi][ni][q] = 0.f;

    uint32_t a_off = (uint32_t)((warp_m*32 + (lane & 15)) * (TSTRIDE*2) + ((lane >> 4) & 1) * 16);
    uint32_t b_off = (uint32_t)((warp_n*32 + (lane & 15)) * (TSTRIDE*2) + ((lane >> 4) & 1) * 16);

    #pragma unroll
    for (int p = 0; p < 3; p++) {
        gram_load_stage(sbase, p, p, ti, tj, ksp, tid, nm);
        cp_commit();
    }

    for (int it = 0; it < KITERS; it++) {
        cp_wait2();
        __syncthreads();

        uint32_t st  = sbase + (it & 3) * STAGE_BY;
        uint32_t aHi = st;
        uint32_t aLo = st + TILE_BY;
        uint32_t bHi = diag ? st           : st + 2*TILE_BY;
        uint32_t bLo = diag ? st + TILE_BY : st + 3*TILE_BY;

        #pragma unroll
        for (int k16 = 0; k16 < 2; k16++) {
            uint32_t kadd = (uint32_t)(k16 * 32);
            uint32_t ahi[2][4], alo[2][4];
            #pragma unroll
            for (int mi = 0; mi < 2; mi++) {
                ldm_x4(ahi[mi], aHi + a_off + kadd + mi*16*(TSTRIDE*2));
                ldm_x4(alo[mi], aLo + a_off + kadd + mi*16*(TSTRIDE*2));
            }
            uint32_t bhiR[2][4], bloR[2][4];
            #pragma unroll
            for (int n2 = 0; n2 < 2; n2++) {
                ldm_x4(bhiR[n2], bHi + b_off + kadd + n2*16*(TSTRIDE*2));
                ldm_x4(bloR[n2], bLo + b_off + kadd + n2*16*(TSTRIDE*2));
            }
            #pragma unroll
            for (int mi = 0; mi < 2; mi++)
                #pragma unroll
                for (int ni = 0; ni < 4; ni++) {
                    int n2 = ni >> 1, sel = ni & 1;
                    uint32_t bh0 = bhiR[n2][sel], bh1 = bhiR[n2][sel+2];
                    uint32_t bl0 = bloR[n2][sel], bl1 = bloR[n2][sel+2];
                    mma_bf16(acc[mi][ni], ahi[mi], bh0, bh1);
                    mma_bf16(acc[mi][ni], ahi[mi], bl0, bl1);
                    mma_bf16(acc[mi][ni], alo[mi], bh0, bh1);
                }
        }

        int nx = it + 3;
        if (nx < KITERS) gram_load_stage(sbase, nx & 3, nx, ti, tj, ksp, tid, nm);
        cp_commit();
    }

    float* dst = &g_gpart[pair][ksp][0];
    int r0 = warp_m * 32;
    int c0 = warp_n * 32;
    #pragma unroll
    for (int mi = 0; mi < 2; mi++) {
        #pragma unroll
        for (int ni = 0; ni < 4; ni++) {
            int row = r0 + mi*16 + (lane >> 2);
            int col = c0 + ni*8 + (lane & 3) * 2;
            *(float2*)&dst[row * 128 + col]       = make_float2(acc[mi][ni][0], acc[mi][ni][1]);
            *(float2*)&dst[(row + 8) * 128 + col] = make_float2(acc[mi][ni][2], acc[mi][ni][3]);
        }
    }
}

// ===========================================================================
// Kernel 4: reduce K-splits, scale, symmetric write
// ===========================================================================
__global__ void gram_reduce_kernel(float* __restrict__ gram) {
    int idx = blockIdx.x * blockDim.x + threadIdx.x;
    if (idx >= GPAIRS * 128 * 128) return;
    int pair = idx >> 14;
    int e    = idx & 16383;
    int ii = e >> 7, jj = e & 127;

    int ti = 0, rem = pair, cnt = GT;
    while (rem >= cnt) { rem -= cnt; ti++; cnt--; }
    int tj = ti + rem;

    int gi = ti * 128 + ii;
    int gj = tj * 128 + jj;
    if (gi >= N_ROWS || gj >= N_ROWS) return;

    float s = 0.f;
    #pragma unroll
    for (int k = 0; k < GKSPLIT; k++) s += g_gpart[pair][k][e];
    s *= (1.0f / 14680064.0f);

    gram[gi * N_ROWS + gj] = s;
    gram[gj * N_ROWS + gi] = s;
}

// ===========================================================================
extern "C" void kernel_launch(void* const* d_in, const int* in_sizes, int n_in,
                              void* d_out, int out_size) {
    const float* image = (const float*)d_in[0];
    const float* pupil = (const float*)d_in[1];
    const float* iris  = (const float*)d_in[2];
    const float* filt  = (const float*)d_in[3];

    float* out   = (float*)d_out;
    float* codes = out + CODES_OFF;
    float* gram  = out + GRAM_OFF;
    float* polar = out + POLAR_OFF;

    cudaFuncSetAttribute(conv_mma_kernel,
                         cudaFuncAttributeMaxDynamicSharedMemorySize, CONV_SMEM);
    cudaFuncSetAttribute(gram_mma_kernel,
                         cudaFuncAttributeMaxDynamicSharedMemorySize, GSMEM);

    polar_kernel<<<(B * PH * PW) / 256, 256>>>(image, pupil, iris, polar);
    conv_mma_kernel<<<dim3(B, PH/8), 256, CONV_SMEM>>>(polar, filt, codes);
    gram_mma_kernel<<<dim3(GPAIRS, GKSPLIT), 512, GSMEM>>>();
    gram_reduce_kernel<<<(GPAIRS * 128 * 128 + 255) / 256, 256>>>(gram);
}

// round 8
// speedup vs baseline: 1.3375x; 1.0169x over previous
#include <cuda_runtime.h>
#include <cuda_bf16.h>
#include <cstdint>

#define B   64
#define H   480
#define W   640
#define PH  64
#define PW  512
#define FS  15
#define NF  7
#define RAD 7

#define K_TOT   (PH*PW)          // 32768
#define N_ROWS  (B*NF)           // 448

#define CODES_OFF 0
#define GRAM_OFF  (B*NF*PH*PW)                // 14680064
#define POLAR_OFF (GRAM_OFF + N_ROWS*N_ROWS)  // 14880768

// ---- gram tiling ----
#define GT       4
#define GPAIRS   10
#define GKSPLIT  64
#define GKCHUNK  (K_TOT/GKSPLIT)    // 512
#define KB       32
#define KITERS   (GKCHUNK/KB)       // 16

#define TSTRIDE  40                 // bf16 per smem row (80B)
#define TILE_BY  (128*TSTRIDE*2)    // 10240 B
#define STAGE_BY (4*TILE_BY)        // 40960 B
#define NSTAGE   2
#define GSMEM    (NSTAGE*STAGE_BY)  // 81920 B -> 2 CTAs/SM

// ---- conv (bf16 implicit GEMM) ----
#define SAB 536                     // bf16 stride per A row
#define SAU 268                     // u32 stride
#define AROWS 22                    // 8 + 14
#define ATILE_U32 (AROWS*SAU)       // 5896
#define CONV_SMEM ((4*ATILE_U32 + 2*960)*4)   // 102016 B

// scratch (device-code references ONLY — host-side symbol use is a silent
// ATS write to host BSS on GB300)
__device__ __nv_bfloat16 g_hi[(size_t)N_ROWS * K_TOT];
__device__ __nv_bfloat16 g_lo[(size_t)N_ROWS * K_TOT];
__device__ float g_gpart[GPAIRS][GKSPLIT][128*128];

// ===========================================================================
// helpers
// ===========================================================================
__device__ __forceinline__ uint32_t smem_u32(const void* p) {
    uint32_t a;
    asm("{ .reg .u64 t; cvta.to.shared.u64 t, %1; cvt.u32.u64 %0, t; }" : "=r"(a) : "l"(p));
    return a;
}

__device__ __forceinline__ void cp16(uint32_t dst, const void* src) {
    asm volatile("cp.async.ca.shared.global [%0], [%1], 16;" :: "r"(dst), "l"(src));
}
__device__ __forceinline__ void cp16z(uint32_t dst, const void* src) {
    asm volatile("cp.async.ca.shared.global [%0], [%1], 16, 0;" :: "r"(dst), "l"(src));
}
__device__ __forceinline__ void cp_commit() { asm volatile("cp.async.commit_group;" ::: "memory"); }
__device__ __forceinline__ void cp_wait1()  { asm volatile("cp.async.wait_group 1;" ::: "memory"); }

__device__ __forceinline__ void ldm_x4(uint32_t* r, uint32_t addr) {
    asm volatile("ldmatrix.sync.aligned.m8n8.x4.shared.b16 {%0,%1,%2,%3}, [%4];"
        : "=r"(r[0]), "=r"(r[1]), "=r"(r[2]), "=r"(r[3]) : "r"(addr));
}
__device__ __forceinline__ void mma_bf16(float* c, const uint32_t* a, uint32_t b0, uint32_t b1) {
    asm volatile("mma.sync.aligned.m16n8k16.row.col.f32.bf16.bf16.f32 "
        "{%0,%1,%2,%3}, {%4,%5,%6,%7}, {%8,%9}, {%0,%1,%2,%3};"
        : "+f"(c[0]), "+f"(c[1]), "+f"(c[2]), "+f"(c[3])
        : "r"(a[0]), "r"(a[1]), "r"(a[2]), "r"(a[3]), "r"(b0), "r"(b1));
}

// ===========================================================================
// Kernel 1: polar bilinear resample
// ===========================================================================
__global__ void polar_kernel(const float* __restrict__ img,
                             const float* __restrict__ pupil,
                             const float* __restrict__ iris,
                             float* __restrict__ polar) {
    int idx = blockIdx.x * blockDim.x + threadIdx.x;
    if (idx >= B * PH * PW) return;
    int col = idx % PW;
    int row = (idx / PW) % PH;
    int b   = idx / (PH * PW);

    float theta = 6.283185307179586f * (float)(col + 1) * (1.0f / (float)PW);
    float ct = cosf(theta), st = sinf(theta);

    float pcx = pupil[b*3+0], pcy = pupil[b*3+1], pr = pupil[b*3+2];
    float icx = iris [b*3+0], icy = iris [b*3+1], ir = iris [b*3+2];

    float px = pcx + pr * ct;
    float py = pcy + pr * st;
    float ix = icx + ir * ct;
    float iy = icy + ir * st;

    float rad = (float)row / (float)(PH - 1);
    float xg = (1.0f - rad) * px + rad * ix;
    float yg = (1.0f - rad) * py + rad * iy;

    float x = fminf(fmaxf(xg, 0.0f), (float)(W - 1));
    float y = fminf(fmaxf(yg, 0.0f), (float)(H - 1));

    float xn = x / (float)(W - 1) * 2.0f - 1.0f;
    float yn = y / (float)(H - 1) * 2.0f - 1.0f;
    float gx = ((xn + 1.0f) * 0.5f * (float)W - 0.5f) / (float)(W - 1) * 2.0f - 1.0f;
    float gy = ((yn + 1.0f) * 0.5f * (float)H - 0.5f) / (float)(H - 1) * 2.0f - 1.0f;
    float sx = ((gx + 1.0f) * (float)W - 1.0f) * 0.5f;
    float sy = ((gy + 1.0f) * (float)H - 1.0f) * 0.5f;

    float x0f = floorf(sx), y0f = floorf(sy);
    float wx = sx - x0f, wy = sy - y0f;
    int x0 = (int)x0f, y0 = (int)y0f;

    const float* im = img + (size_t)b * H * W;

    float v00 = 0.f, v01 = 0.f, v10 = 0.f, v11 = 0.f;
    bool xv0 = (x0 >= 0) && (x0 < W);
    bool xv1 = (x0+1 >= 0) && (x0+1 < W);
    bool yv0 = (y0 >= 0) && (y0 < H);
    bool yv1 = (y0+1 >= 0) && (y0+1 < H);
    int x0c = min(max(x0, 0), W-1), x1c = min(max(x0+1, 0), W-1);
    int y0c = min(max(y0, 0), H-1), y1c = min(max(y0+1, 0), H-1);
    if (xv0 && yv0) v00 = im[y0c*W + x0c] * 255.0f;
    if (xv1 && yv0) v01 = im[y0c*W + x1c] * 255.0f;
    if (xv0 && yv1) v10 = im[y1c*W + x0c] * 255.0f;
    if (xv1 && yv1) v11 = im[y1c*W + x1c] * 255.0f;

    float v = v00*(1.0f-wx)*(1.0f-wy) + v01*wx*(1.0f-wy)
            + v10*(1.0f-wx)*wy        + v11*wx*wy;
    polar[idx] = v;
}

// ===========================================================================
// Kernel 2: conv as bf16 implicit GEMM (hi/lo 3-term split). (unchanged R7)
// ===========================================================================
__global__ __launch_bounds__(256, 2)
void conv_mma_kernel(const float* __restrict__ polar,
                     const float* __restrict__ filt,
                     float* __restrict__ codes) {
    extern __shared__ uint32_t cs[];
    uint32_t* aHE = cs;
    uint32_t* aHO = cs + ATILE_U32;
    uint32_t* aLE = cs + 2*ATILE_U32;
    uint32_t* aLO = cs + 3*ATILE_U32;
    uint32_t* BsH = cs + 4*ATILE_U32;
    uint32_t* BsL = BsH + 960;

    int b  = blockIdx.x;
    int y0 = blockIdx.y * 8;
    int tid = threadIdx.x, wid = tid >> 5, lane = tid & 31;

    for (int e = tid; e < 960; e += 256) {
        int i = e >> 6, kp = (e >> 3) & 7, n = e & 7;
        int k0 = 2*kp, k1 = 2*kp + 1;
        float w0 = (k0 < FS && n < NF) ? filt[(i*FS + k0)*NF + (6 - n)] : 0.f;
        float w1 = (k1 < FS && n < NF) ? filt[(i*FS + k1)*NF + (6 - n)] : 0.f;
        __nv_bfloat16 h0 = __float2bfloat16(w0);
        __nv_bfloat16 h1 = __float2bfloat16(w1);
        __nv_bfloat16 l0 = __float2bfloat16(w0 - __bfloat162float(h0));
        __nv_bfloat16 l1 = __float2bfloat16(w1 - __bfloat162float(h1));
        BsH[e] = ((uint32_t)__bfloat16_as_ushort(h1) << 16) | __bfloat16_as_ushort(h0);
        BsL[e] = ((uint32_t)__bfloat16_as_ushort(l1) << 16) | __bfloat16_as_ushort(l0);
    }
    const float* pb = polar + (size_t)b * PH * PW;
    __nv_bfloat16* aHEh = (__nv_bfloat16*)aHE;
    __nv_bfloat16* aHOh = (__nv_bfloat16*)aHO;
    __nv_bfloat16* aLEh = (__nv_bfloat16*)aLE;
    __nv_bfloat16* aLOh = (__nv_bfloat16*)aLO;
    for (int e = tid; e < AROWS * 529; e += 256) {
        int r = e / 529, c = e % 529;
        int gy = (y0 - RAD + r) & (PH - 1);
        int gx = (c - RAD) & (PW - 1);
        float v = pb[gy*PW + gx];
        __nv_bfloat16 h = __float2bfloat16(v);
        __nv_bfloat16 l = __float2bfloat16(v - __bfloat162float(h));
        aHEh[r*SAB + c] = h;
        aLEh[r*SAB + c] = l;
        if (c > 0) { aHOh[r*SAB + c - 1] = h; aLOh[r*SAB + c - 1] = l; }
    }
    __syncthreads();

    int yl = wid;
    int pe = (lane >> 2) & 1;
    int lofs = ((lane >> 2) >> 1) + (lane & 3);
    const uint32_t* pHbase = pe ? aHO : aHE;
    const uint32_t* pLbase = pe ? aLO : aLE;
    int bi0 = (lane & 3)*8 + (lane >> 2);

    for (int xt = 0; xt < 8; xt++) {
        int x0 = xt * 64;
        int xofs = x0 >> 1;
        float acc[4][4];
        #pragma unroll
        for (int mf = 0; mf < 4; mf++)
            acc[mf][0] = acc[mf][1] = acc[mf][2] = acc[mf][3] = 0.f;

        #pragma unroll 1
        for (int i = 0; i < FS; i++) {
            const uint32_t* pH = pHbase + (yl + i)*SAU + xofs + lofs;
            const uint32_t* pL = pLbase + (yl + i)*SAU + xofs + lofs;
            uint32_t vh[9], vl[9];
            #pragma unroll
            for (int s = 0; s < 9; s++) { vh[s] = pH[4*s]; vl[s] = pL[4*s]; }
            uint32_t bh0 = BsH[i*64 + bi0];
            uint32_t bh1 = BsH[i*64 + bi0 + 32];
            uint32_t bl0 = BsL[i*64 + bi0];
            uint32_t bl1 = BsL[i*64 + bi0 + 32];
            #pragma unroll
            for (int mf = 0; mf < 4; mf++) {
                uint32_t ah[4] = {vh[2*mf], vh[2*mf+1], vh[2*mf+1], vh[2*mf+2]};
                uint32_t al[4] = {vl[2*mf], vl[2*mf+1], vl[2*mf+1], vl[2*mf+2]};
                mma_bf16(acc[mf], ah, bh0, bh1);
                mma_bf16(acc[mf], ah, bl0, bl1);
                mma_bf16(acc[mf], al, bh0, bh1);
            }
        }

        int y = y0 + yl;
        int n0 = 2*(lane & 3);
        #pragma unroll
        for (int mf = 0; mf < 4; mf++) {
            int xa = x0 + mf*16 + (lane >> 2);
            #pragma unroll
            for (int q = 0; q < 4; q++) {
                int o = n0 + (q & 1);
                if (o >= NF) continue;
                int x = xa + (q >> 1)*8;
                float v = acc[mf][q];
                size_t off = (((size_t)(b*NF + o))*PH + y)*PW + x;
                codes[off] = v;
                __nv_bfloat16 hh = __float2bfloat16(v);
                g_hi[off] = hh;
                g_lo[off] = __float2bfloat16(v - __bfloat162float(hh));
            }
        }
    }
}

// ===========================================================================
// Kernel 3: gram via mma.sync bf16 (hi/lo, 3 terms), 16 warps.
// 2-stage ring (81920 B smem -> 2 CTAs/SM), load-before-compute, KSPLIT=64.
// ===========================================================================
__device__ __forceinline__ void gram_load_stage(uint32_t sbase, int stage, int it,
                                                int ti, int tj, int ksp, int tid, int nm) {
    uint32_t st = sbase + stage * STAGE_BY;
    size_t kbyte = ((size_t)ksp * GKCHUNK + (size_t)it * KB) * 2;
    int row = tid >> 2, k8 = tid & 3;
    uint32_t doff = (uint32_t)(row * (TSTRIDE*2) + k8 * 16);
    #pragma unroll
    for (int m = 0; m < 4; m++) {
        if (m >= nm) break;
        int grow = ((m < 2) ? ti : tj) * 128 + row;
        const char* matbase = (m & 1) ? (const char*)g_lo : (const char*)g_hi;
        uint32_t dst = st + m * TILE_BY + doff;
        const char* src = matbase + (size_t)min(grow, N_ROWS-1) * (K_TOT*2) + kbyte + k8 * 16;
        if (grow < N_ROWS) cp16(dst, src);
        else               cp16z(dst, src);
    }
}

__global__ __launch_bounds__(512, 2)
void gram_mma_kernel() {
    extern __shared__ char dsm[];
    uint32_t sbase = smem_u32(dsm);

    int pair = blockIdx.x;
    int ksp  = blockIdx.y;
    int ti = 0, rem = pair, cnt = GT;
    while (rem >= cnt) { rem -= cnt; ti++; cnt--; }
    int tj = ti + rem;
    bool diag = (ti == tj);
    int nm = diag ? 2 : 4;

    int tid  = threadIdx.x;
    int wid  = tid >> 5, lane = tid & 31;
    int warp_m = wid & 3;
    int warp_n = wid >> 2;

    float acc[2][4][4];
    #pragma unroll
    for (int mi = 0; mi < 2; mi++)
        #pragma unroll
        for (int ni = 0; ni < 4; ni++)
            #pragma unroll
            for (int q = 0; q < 4; q++) acc[mi][ni][q] = 0.f;

    uint32_t a_off = (uint32_t)((warp_m*32 + (lane & 15)) * (TSTRIDE*2) + ((lane >> 4) & 1) * 16);
    uint32_t b_off = (uint32_t)((warp_n*32 + (lane & 15)) * (TSTRIDE*2) + ((lane >> 4) & 1) * 16);

    // prologue: stage 0 in flight
    gram_load_stage(sbase, 0, 0, ti, tj, ksp, tid, nm);
    cp_commit();

    for (int it = 0; it < KITERS; it++) {
        // prefetch next stage BEFORE compute (target buffer was consumed at it-1,
        // fenced by the end-of-iter sync)
        int nx = it + 1;
        if (nx < KITERS) gram_load_stage(sbase, nx & 1, nx, ti, tj, ksp, tid, nm);
        cp_commit();
        cp_wait1();                 // stage `it` ready, stage `it+1` in flight
        __syncthreads();

        uint32_t st  = sbase + (it & 1) * STAGE_BY;
        uint32_t aHi = st;
        uint32_t aLo = st + TILE_BY;
        uint32_t bHi = diag ? st           : st + 2*TILE_BY;
        uint32_t bLo = diag ? st + TILE_BY : st + 3*TILE_BY;

        #pragma unroll
        for (int k16 = 0; k16 < 2; k16++) {
            uint32_t kadd = (uint32_t)(k16 * 32);
            uint32_t ahi[2][4], alo[2][4];
            #pragma unroll
            for (int mi = 0; mi < 2; mi++) {
                ldm_x4(ahi[mi], aHi + a_off + kadd + mi*16*(TSTRIDE*2));
                ldm_x4(alo[mi], aLo + a_off + kadd + mi*16*(TSTRIDE*2));
            }
            uint32_t bhiR[2][4], bloR[2][4];
            #pragma unroll
            for (int n2 = 0; n2 < 2; n2++) {
                ldm_x4(bhiR[n2], bHi + b_off + kadd + n2*16*(TSTRIDE*2));
                ldm_x4(bloR[n2], bLo + b_off + kadd + n2*16*(TSTRIDE*2));
            }
            #pragma unroll
            for (int mi = 0; mi < 2; mi++)
                #pragma unroll
                for (int ni = 0; ni < 4; ni++) {
                    int n2 = ni >> 1, sel = ni & 1;
                    uint32_t bh0 = bhiR[n2][sel], bh1 = bhiR[n2][sel+2];
                    uint32_t bl0 = bloR[n2][sel], bl1 = bloR[n2][sel+2];
                    mma_bf16(acc[mi][ni], ahi[mi], bh0, bh1);
                    mma_bf16(acc[mi][ni], ahi[mi], bl0, bl1);
                    mma_bf16(acc[mi][ni], alo[mi], bh0, bh1);
                }
        }
        __syncthreads();            // all warps done with stage `it` buffer
    }

    float* dst = &g_gpart[pair][ksp][0];
    int r0 = warp_m * 32;
    int c0 = warp_n * 32;
    #pragma unroll
    for (int mi = 0; mi < 2; mi++) {
        #pragma unroll
        for (int ni = 0; ni < 4; ni++) {
            int row = r0 + mi*16 + (lane >> 2);
            int col = c0 + ni*8 + (lane & 3) * 2;
            *(float2*)&dst[row * 128 + col]       = make_float2(acc[mi][ni][0], acc[mi][ni][1]);
            *(float2*)&dst[(row + 8) * 128 + col] = make_float2(acc[mi][ni][2], acc[mi][ni][3]);
        }
    }
}

// ===========================================================================
// Kernel 4: reduce K-splits, scale, symmetric write
// ===========================================================================
__global__ void gram_reduce_kernel(float* __restrict__ gram) {
    int idx = blockIdx.x * blockDim.x + threadIdx.x;
    if (idx >= GPAIRS * 128 * 128) return;
    int pair = idx >> 14;
    int e    = idx & 16383;
    int ii = e >> 7, jj = e & 127;

    int ti = 0, rem = pair, cnt = GT;
    while (rem >= cnt) { rem -= cnt; ti++; cnt--; }
    int tj = ti + rem;

    int gi = ti * 128 + ii;
    int gj = tj * 128 + jj;
    if (gi >= N_ROWS || gj >= N_ROWS) return;

    float s = 0.f;
    #pragma unroll
    for (int k = 0; k < GKSPLIT; k++) s += g_gpart[pair][k][e];
    s *= (1.0f / 14680064.0f);

    gram[gi * N_ROWS + gj] = s;
    gram[gj * N_ROWS + gi] = s;
}

// ===========================================================================
extern "C" void kernel_launch(void* const* d_in, const int* in_sizes, int n_in,
                              void* d_out, int out_size) {
    const float* image = (const float*)d_in[0];
    const float* pupil = (const float*)d_in[1];
    const float* iris  = (const float*)d_in[2];
    const float* filt  = (const float*)d_in[3];

    float* out   = (float*)d_out;
    float* codes = out + CODES_OFF;
    float* gram  = out + GRAM_OFF;
    float* polar = out + POLAR_OFF;

    cudaFuncSetAttribute(conv_mma_kernel,
                         cudaFuncAttributeMaxDynamicSharedMemorySize, CONV_SMEM);
    cudaFuncSetAttribute(gram_mma_kernel,
                         cudaFuncAttributeMaxDynamicSharedMemorySize, GSMEM);

    polar_kernel<<<(B * PH * PW) / 256, 256>>>(image, pupil, iris, polar);
    conv_mma_kernel<<<dim3(B, PH/8), 256, CONV_SMEM>>>(polar, filt, codes);
    gram_mma_kernel<<<dim3(GPAIRS, GKSPLIT), 512, GSMEM>>>();
    gram_reduce_kernel<<<(GPAIRS * 128 * 128 + 255) / 256, 256>>>(gram);
}

// round 9
// speedup vs baseline: 2.4645x; 1.8426x over previous
#include <cuda_runtime.h>
#include <cuda_fp16.h>
#include <cstdint>

#define B   64
#define H   480
#define W   640
#define PH  64
#define PW  512
#define FS  15
#define NF  7
#define RAD 7

#define K_TOT   (PH*PW)          // 32768
#define N_ROWS  (B*NF)           // 448

#define CODES_OFF 0
#define GRAM_OFF  (B*NF*PH*PW)                // 14680064
#define POLAR_OFF (GRAM_OFF + N_ROWS*N_ROWS)  // 14880768

#define FSCALE      0.0625f                   // feats stored * 1/16
#define GRAM_SCALE  (256.0f / 14680064.0f)    // undo FSCALE^2 and normalize

// ---- gram tiling ----
#define GT       4
#define GPAIRS   10
#define GKSPLIT  64
#define GKCHUNK  (K_TOT/GKSPLIT)    // 512
#define KB       32
#define KITERS   (GKCHUNK/KB)       // 16

#define TSTRIDE  40                 // fp16 per smem row (80B)
#define TILE_BY  (128*TSTRIDE*2)    // 10240 B
#define STAGE_BY (2*TILE_BY)        // 20480 B (A|B, single term)
#define NSTAGE   4
#define GSMEM    (NSTAGE*STAGE_BY)  // 81920 B -> 2 CTAs/SM

// ---- conv (fp16 implicit GEMM, A single / B hi+lo) ----
#define SAB 536                     // fp16 stride per A row
#define SAU 268                     // u32 stride
#define AROWS 22                    // 8 + 14
#define ATILE_U32 (AROWS*SAU)       // 5896
#define CONV_SMEM ((2*ATILE_U32 + 2*960)*4)   // 54848 B -> 4 CTAs/SM

// scratch (device-code references ONLY — host-side symbol use is a silent
// ATS write to host BSS on GB300)
__device__ __half g_h[(size_t)N_ROWS * K_TOT];
__device__ float g_gpart[GPAIRS][GKSPLIT][128*128];

// ===========================================================================
// helpers
// ===========================================================================
__device__ __forceinline__ uint32_t smem_u32(const void* p) {
    uint32_t a;
    asm("{ .reg .u64 t; cvta.to.shared.u64 t, %1; cvt.u32.u64 %0, t; }" : "=r"(a) : "l"(p));
    return a;
}

__device__ __forceinline__ void cp16(uint32_t dst, const void* src) {
    asm volatile("cp.async.ca.shared.global [%0], [%1], 16;" :: "r"(dst), "l"(src));
}
__device__ __forceinline__ void cp16z(uint32_t dst, const void* src) {
    asm volatile("cp.async.ca.shared.global [%0], [%1], 16, 0;" :: "r"(dst), "l"(src));
}
__device__ __forceinline__ void cp_commit() { asm volatile("cp.async.commit_group;" ::: "memory"); }
__device__ __forceinline__ void cp_wait2()  { asm volatile("cp.async.wait_group 2;" ::: "memory"); }

__device__ __forceinline__ void ldm_x4(uint32_t* r, uint32_t addr) {
    asm volatile("ldmatrix.sync.aligned.m8n8.x4.shared.b16 {%0,%1,%2,%3}, [%4];"
        : "=r"(r[0]), "=r"(r[1]), "=r"(r[2]), "=r"(r[3]) : "r"(addr));
}
__device__ __forceinline__ void mma_f16(float* c, const uint32_t* a, uint32_t b0, uint32_t b1) {
    asm volatile("mma.sync.aligned.m16n8k16.row.col.f32.f16.f16.f32 "
        "{%0,%1,%2,%3}, {%4,%5,%6,%7}, {%8,%9}, {%0,%1,%2,%3};"
        : "+f"(c[0]), "+f"(c[1]), "+f"(c[2]), "+f"(c[3])
        : "r"(a[0]), "r"(a[1]), "r"(a[2]), "r"(a[3]), "r"(b0), "r"(b1));
}

// ===========================================================================
// Kernel 1: polar bilinear resample
// ===========================================================================
__global__ void polar_kernel(const float* __restrict__ img,
                             const float* __restrict__ pupil,
                             const float* __restrict__ iris,
                             float* __restrict__ polar) {
    int idx = blockIdx.x * blockDim.x + threadIdx.x;
    if (idx >= B * PH * PW) return;
    int col = idx % PW;
    int row = (idx / PW) % PH;
    int b   = idx / (PH * PW);

    float theta = 6.283185307179586f * (float)(col + 1) * (1.0f / (float)PW);
    float ct = cosf(theta), st = sinf(theta);

    float pcx = pupil[b*3+0], pcy = pupil[b*3+1], pr = pupil[b*3+2];
    float icx = iris [b*3+0], icy = iris [b*3+1], ir = iris [b*3+2];

    float px = pcx + pr * ct;
    float py = pcy + pr * st;
    float ix = icx + ir * ct;
    float iy = icy + ir * st;

    float rad = (float)row / (float)(PH - 1);
    float xg = (1.0f - rad) * px + rad * ix;
    float yg = (1.0f - rad) * py + rad * iy;

    float x = fminf(fmaxf(xg, 0.0f), (float)(W - 1));
    float y = fminf(fmaxf(yg, 0.0f), (float)(H - 1));

    float xn = x / (float)(W - 1) * 2.0f - 1.0f;
    float yn = y / (float)(H - 1) * 2.0f - 1.0f;
    float gx = ((xn + 1.0f) * 0.5f * (float)W - 0.5f) / (float)(W - 1) * 2.0f - 1.0f;
    float gy = ((yn + 1.0f) * 0.5f * (float)H - 0.5f) / (float)(H - 1) * 2.0f - 1.0f;
    float sx = ((gx + 1.0f) * (float)W - 1.0f) * 0.5f;
    float sy = ((gy + 1.0f) * (float)H - 1.0f) * 0.5f;

    float x0f = floorf(sx), y0f = floorf(sy);
    float wx = sx - x0f, wy = sy - y0f;
    int x0 = (int)x0f, y0 = (int)y0f;

    const float* im = img + (size_t)b * H * W;

    float v00 = 0.f, v01 = 0.f, v10 = 0.f, v11 = 0.f;
    bool xv0 = (x0 >= 0) && (x0 < W);
    bool xv1 = (x0+1 >= 0) && (x0+1 < W);
    bool yv0 = (y0 >= 0) && (y0 < H);
    bool yv1 = (y0+1 >= 0) && (y0+1 < H);
    int x0c = min(max(x0, 0), W-1), x1c = min(max(x0+1, 0), W-1);
    int y0c = min(max(y0, 0), H-1), y1c = min(max(y0+1, 0), H-1);
    if (xv0 && yv0) v00 = im[y0c*W + x0c] * 255.0f;
    if (xv1 && yv0) v01 = im[y0c*W + x1c] * 255.0f;
    if (xv0 && yv1) v10 = im[y1c*W + x0c] * 255.0f;
    if (xv1 && yv1) v11 = im[y1c*W + x1c] * 255.0f;

    float v = v00*(1.0f-wx)*(1.0f-wy) + v01*wx*(1.0f-wy)
            + v10*(1.0f-wx)*wy        + v11*wx*wy;
    polar[idx] = v;
}

// ===========================================================================
// Kernel 2: conv as fp16 implicit GEMM. A single fp16 (pixel rounding
// averages across K=225); B split hi+lo fp16 (weights exact to ~1e-7).
// 2 MMA terms per fragment. Block (b, y-strip of 8), 256 thr / 8 warps.
// ===========================================================================
__global__ __launch_bounds__(256, 4)
void conv_mma_kernel(const float* __restrict__ polar,
                     const float* __restrict__ filt,
                     float* __restrict__ codes) {
    extern __shared__ uint32_t cs[];
    uint32_t* aE  = cs;
    uint32_t* aO  = cs + ATILE_U32;
    uint32_t* BsH = cs + 2*ATILE_U32;
    uint32_t* BsL = BsH + 960;

    int b  = blockIdx.x;
    int y0 = blockIdx.y * 8;
    int tid = threadIdx.x, wid = tid >> 5, lane = tid & 31;

    // B fill: BsH/BsL[i][kp][n] = fp16x2 (k=2kp,2kp+1), n->o flip baked in
    for (int e = tid; e < 960; e += 256) {
        int i = e >> 6, kp = (e >> 3) & 7, n = e & 7;
        int k0 = 2*kp, k1 = 2*kp + 1;
        float w0 = (k0 < FS && n < NF) ? filt[(i*FS + k0)*NF + (6 - n)] : 0.f;
        float w1 = (k1 < FS && n < NF) ? filt[(i*FS + k1)*NF + (6 - n)] : 0.f;
        __half h0 = __float2half(w0);
        __half h1 = __float2half(w1);
        __half l0 = __float2half(w0 - __half2float(h0));
        __half l1 = __float2half(w1 - __half2float(h1));
        BsH[e] = ((uint32_t)__half_as_ushort(h1) << 16) | __half_as_ushort(h0);
        BsL[e] = ((uint32_t)__half_as_ushort(l1) << 16) | __half_as_ushort(l0);
    }
    // A fill: 22 rows x 529 cols (wrap), even + odd-shift fp16 copies
    const float* pb = polar + (size_t)b * PH * PW;
    __half* aEh = (__half*)aE;
    __half* aOh = (__half*)aO;
    for (int e = tid; e < AROWS * 529; e += 256) {
        int r = e / 529, c = e % 529;
        int gy = (y0 - RAD + r) & (PH - 1);
        int gx = (c - RAD) & (PW - 1);
        __half h = __float2half(pb[gy*PW + gx]);
        aEh[r*SAB + c] = h;
        if (c > 0) aOh[r*SAB + c - 1] = h;
    }
    __syncthreads();

    int yl = wid;
    int pe = (lane >> 2) & 1;
    int lofs = ((lane >> 2) >> 1) + (lane & 3);
    const uint32_t* pAbase = pe ? aO : aE;
    int bi0 = (lane & 3)*8 + (lane >> 2);

    for (int xt = 0; xt < 8; xt++) {
        int x0 = xt * 64;
        int xofs = x0 >> 1;
        float acc[4][4];
        #pragma unroll
        for (int mf = 0; mf < 4; mf++)
            acc[mf][0] = acc[mf][1] = acc[mf][2] = acc[mf][3] = 0.f;

        #pragma unroll 1
        for (int i = 0; i < FS; i++) {
            const uint32_t* pA = pAbase + (yl + i)*SAU + xofs + lofs;
            uint32_t va[9];
            #pragma unroll
            for (int s = 0; s < 9; s++) va[s] = pA[4*s];
            uint32_t bh0 = BsH[i*64 + bi0];
            uint32_t bh1 = BsH[i*64 + bi0 + 32];
            uint32_t bl0 = BsL[i*64 + bi0];
            uint32_t bl1 = BsL[i*64 + bi0 + 32];
            #pragma unroll
            for (int mf = 0; mf < 4; mf++) {
                uint32_t a[4] = {va[2*mf], va[2*mf+1], va[2*mf+1], va[2*mf+2]};
                mma_f16(acc[mf], a, bh0, bh1);
                mma_f16(acc[mf], a, bl0, bl1);
            }
        }

        int y = y0 + yl;
        int n0 = 2*(lane & 3);
        #pragma unroll
        for (int mf = 0; mf < 4; mf++) {
            int xa = x0 + mf*16 + (lane >> 2);
            #pragma unroll
            for (int q = 0; q < 4; q++) {
                int o = n0 + (q & 1);
                if (o >= NF) continue;
                int x = xa + (q >> 1)*8;
                float v = acc[mf][q];
                size_t off = (((size_t)(b*NF + o))*PH + y)*PW + x;
                codes[off] = v;
                g_h[off] = __float2half(v * FSCALE);
            }
        }
    }
}

// ===========================================================================
// Kernel 3: gram via mma.sync fp16 single-term, 16 warps, 4-stage ring,
// one sync per iter.
// ===========================================================================
__device__ __forceinline__ void gram_load_stage(uint32_t sbase, int stage, int it,
                                                int ti, int tj, int ksp, int tid, int nm) {
    uint32_t st = sbase + stage * STAGE_BY;
    size_t kbyte = ((size_t)ksp * GKCHUNK + (size_t)it * KB) * 2;
    int row = tid >> 2, k8 = tid & 3;
    uint32_t doff = (uint32_t)(row * (TSTRIDE*2) + k8 * 16);
    #pragma unroll
    for (int m = 0; m < 2; m++) {
        if (m >= nm) break;
        int grow = ((m == 0) ? ti : tj) * 128 + row;
        uint32_t dst = st + m * TILE_BY + doff;
        const char* src = (const char*)g_h + (size_t)min(grow, N_ROWS-1) * (K_TOT*2) + kbyte + k8 * 16;
        if (grow < N_ROWS) cp16(dst, src);
        else               cp16z(dst, src);
    }
}

__global__ __launch_bounds__(512, 2)
void gram_mma_kernel() {
    extern __shared__ char dsm[];
    uint32_t sbase = smem_u32(dsm);

    int pair = blockIdx.x;
    int ksp  = blockIdx.y;
    int ti = 0, rem = pair, cnt = GT;
    while (rem >= cnt) { rem -= cnt; ti++; cnt--; }
    int tj = ti + rem;
    bool diag = (ti == tj);
    int nm = diag ? 1 : 2;

    int tid  = threadIdx.x;
    int wid  = tid >> 5, lane = tid & 31;
    int warp_m = wid & 3;
    int warp_n = wid >> 2;

    float acc[2][4][4];
    #pragma unroll
    for (int mi = 0; mi < 2; mi++)
        #pragma unroll
        for (int ni = 0; ni < 4; ni++)
            #pragma unroll
            for (int q = 0; q < 4; q++) acc[mi][ni][q] = 0.f;

    uint32_t a_off = (uint32_t)((warp_m*32 + (lane & 15)) * (TSTRIDE*2) + ((lane >> 4) & 1) * 16);
    uint32_t b_off = (uint32_t)((warp_n*32 + (lane & 15)) * (TSTRIDE*2) + ((lane >> 4) & 1) * 16);

    // prologue: stages 0..2 in flight
    #pragma unroll
    for (int p = 0; p < 3; p++) {
        gram_load_stage(sbase, p, p, ti, tj, ksp, tid, nm);
        cp_commit();
    }

    for (int it = 0; it < KITERS; it++) {
        cp_wait2();               // stage `it` complete; it+1, it+2 pending
        __syncthreads();          // also fences reads of buffer (it-1)&3

        // prefetch stage it+3 into buffer (it-1)&3 (free since last iter)
        int nx = it + 3;
        if (nx < KITERS) gram_load_stage(sbase, nx & 3, nx, ti, tj, ksp, tid, nm);
        cp_commit();

        uint32_t st = sbase + (it & 3) * STAGE_BY;
        uint32_t aB = st;
        uint32_t bB = diag ? st : st + TILE_BY;

        #pragma unroll
        for (int k16 = 0; k16 < 2; k16++) {
            uint32_t kadd = (uint32_t)(k16 * 32);
            uint32_t af[2][4], bf[2][4];
            #pragma unroll
            for (int mi = 0; mi < 2; mi++)
                ldm_x4(af[mi], aB + a_off + kadd + mi*16*(TSTRIDE*2));
            #pragma unroll
            for (int n2 = 0; n2 < 2; n2++)
                ldm_x4(bf[n2], bB + b_off + kadd + n2*16*(TSTRIDE*2));
            #pragma unroll
            for (int mi = 0; mi < 2; mi++)
                #pragma unroll
                for (int ni = 0; ni < 4; ni++) {
                    int n2 = ni >> 1, sel = ni & 1;
                    mma_f16(acc[mi][ni], af[mi], bf[n2][sel], bf[n2][sel+2]);
                }
        }
    }

    float* dst = &g_gpart[pair][ksp][0];
    int r0 = warp_m * 32;
    int c0 = warp_n * 32;
    #pragma unroll
    for (int mi = 0; mi < 2; mi++) {
        #pragma unroll
        for (int ni = 0; ni < 4; ni++) {
            int row = r0 + mi*16 + (lane >> 2);
            int col = c0 + ni*8 + (lane & 3) * 2;
            *(float2*)&dst[row * 128 + col]       = make_float2(acc[mi][ni][0], acc[mi][ni][1]);
            *(float2*)&dst[(row + 8) * 128 + col] = make_float2(acc[mi][ni][2], acc[mi][ni][3]);
        }
    }
}

// ===========================================================================
// Kernel 4: reduce K-splits, scale, symmetric write
// ===========================================================================
__global__ void gram_reduce_kernel(float* __restrict__ gram) {
    int idx = blockIdx.x * blockDim.x + threadIdx.x;
    if (idx >= GPAIRS * 128 * 128) return;
    int pair = idx >> 14;
    int e    = idx & 16383;
    int ii = e >> 7, jj = e & 127;

    int ti = 0, rem = pair, cnt = GT;
    while (rem >= cnt) { rem -= cnt; ti++; cnt--; }
    int tj = ti + rem;

    int gi = ti * 128 + ii;
    int gj = tj * 128 + jj;
    if (gi >= N_ROWS || gj >= N_ROWS) return;

    float s = 0.f;
    #pragma unroll
    for (int k = 0; k < GKSPLIT; k++) s += g_gpart[pair][k][e];
    s *= GRAM_SCALE;

    gram[gi * N_ROWS + gj] = s;
    gram[gj * N_ROWS + gi] = s;
}

// ===========================================================================
extern "C" void kernel_launch(void* const* d_in, const int* in_sizes, int n_in,
                              void* d_out, int out_size) {
    const float* image = (const float*)d_in[0];
    const float* pupil = (const float*)d_in[1];
    const float* iris  = (const float*)d_in[2];
    const float* filt  = (const float*)d_in[3];

    float* out   = (float*)d_out;
    float* codes = out + CODES_OFF;
    float* gram  = out + GRAM_OFF;
    float* polar = out + POLAR_OFF;

    cudaFuncSetAttribute(conv_mma_kernel,
                         cudaFuncAttributeMaxDynamicSharedMemorySize, CONV_SMEM);
    cudaFuncSetAttribute(gram_mma_kernel,
                         cudaFuncAttributeMaxDynamicSharedMemorySize, GSMEM);

    polar_kernel<<<(B * PH * PW) / 256, 256>>>(image, pupil, iris, polar);
    conv_mma_kernel<<<dim3(B, PH/8), 256, CONV_SMEM>>>(polar, filt, codes);
    gram_mma_kernel<<<dim3(GPAIRS, GKSPLIT), 512, GSMEM>>>();
    gram_reduce_kernel<<<(GPAIRS * 128 * 128 + 255) / 256, 256>>>(gram);
}

// round 10
// speedup vs baseline: 2.5744x; 1.0446x over previous
#include <cuda_runtime.h>
#include <cuda_fp16.h>
#include <cstdint>

#define B   64
#define H   480
#define W   640
#define PH  64
#define PW  512
#define FS  15
#define NF  7
#define RAD 7

#define K_TOT   (PH*PW)          // 32768
#define N_ROWS  (B*NF)           // 448

#define CODES_OFF 0
#define GRAM_OFF  (B*NF*PH*PW)                // 14680064
#define POLAR_OFF (GRAM_OFF + N_ROWS*N_ROWS)  // 14880768

#define FSCALE      0.0625f                   // feats stored * 1/16
#define GRAM_SCALE  (256.0f / 14680064.0f)    // undo FSCALE^2 and normalize

// ---- gram tiling ----
#define GT       4
#define GPAIRS   10
#define GKSPLIT  64
#define GKCHUNK  (K_TOT/GKSPLIT)    // 512
#define KB       32
#define KITERS   (GKCHUNK/KB)       // 16

#define TSTRIDE  40                 // fp16 per smem row (80B)
#define TILE_BY  (128*TSTRIDE*2)    // 10240 B
#define STAGE_BY (2*TILE_BY)        // 20480 B (A|B, single term)
#define NSTAGE   4
#define GSMEM    (NSTAGE*STAGE_BY)  // 81920 B -> 2 CTAs/SM

// ---- conv (fp16 implicit GEMM, single term) ----
#define SAB 536                     // fp16 stride per A row
#define SAU 268                     // u32 stride
#define AROWS 22                    // 8 + 14
#define ATILE_U32 (AROWS*SAU)       // 5896
#define CONV_SMEM ((2*ATILE_U32 + 960)*4)     // 51008 B -> 4 CTAs/SM

// scratch (device-code references ONLY — host-side symbol use is a silent
// ATS write to host BSS on GB300)
__device__ __half g_h[(size_t)N_ROWS * K_TOT];
__device__ float g_gpart[GPAIRS][GKSPLIT][128*128];

// ===========================================================================
// helpers
// ===========================================================================
__device__ __forceinline__ uint32_t smem_u32(const void* p) {
    uint32_t a;
    asm("{ .reg .u64 t; cvta.to.shared.u64 t, %1; cvt.u32.u64 %0, t; }" : "=r"(a) : "l"(p));
    return a;
}

__device__ __forceinline__ void cp16(uint32_t dst, const void* src) {
    asm volatile("cp.async.ca.shared.global [%0], [%1], 16;" :: "r"(dst), "l"(src));
}
__device__ __forceinline__ void cp16z(uint32_t dst, const void* src) {
    asm volatile("cp.async.ca.shared.global [%0], [%1], 16, 0;" :: "r"(dst), "l"(src));
}
__device__ __forceinline__ void cp_commit() { asm volatile("cp.async.commit_group;" ::: "memory"); }
__device__ __forceinline__ void cp_wait2()  { asm volatile("cp.async.wait_group 2;" ::: "memory"); }

__device__ __forceinline__ void ldm_x4(uint32_t* r, uint32_t addr) {
    asm volatile("ldmatrix.sync.aligned.m8n8.x4.shared.b16 {%0,%1,%2,%3}, [%4];"
        : "=r"(r[0]), "=r"(r[1]), "=r"(r[2]), "=r"(r[3]) : "r"(addr));
}
__device__ __forceinline__ void mma_f16(float* c, const uint32_t* a, uint32_t b0, uint32_t b1) {
    asm volatile("mma.sync.aligned.m16n8k16.row.col.f32.f16.f16.f32 "
        "{%0,%1,%2,%3}, {%4,%5,%6,%7}, {%8,%9}, {%0,%1,%2,%3};"
        : "+f"(c[0]), "+f"(c[1]), "+f"(c[2]), "+f"(c[3])
        : "r"(a[0]), "r"(a[1]), "r"(a[2]), "r"(a[3]), "r"(b0), "r"(b1));
}

// ===========================================================================
// Kernel 1: polar bilinear resample
// ===========================================================================
__global__ void polar_kernel(const float* __restrict__ img,
                             const float* __restrict__ pupil,
                             const float* __restrict__ iris,
                             float* __restrict__ polar) {
    int idx = blockIdx.x * blockDim.x + threadIdx.x;
    if (idx >= B * PH * PW) return;
    int col = idx % PW;
    int row = (idx / PW) % PH;
    int b   = idx / (PH * PW);

    float theta = 6.283185307179586f * (float)(col + 1) * (1.0f / (float)PW);
    float ct = cosf(theta), st = sinf(theta);

    float pcx = pupil[b*3+0], pcy = pupil[b*3+1], pr = pupil[b*3+2];
    float icx = iris [b*3+0], icy = iris [b*3+1], ir = iris [b*3+2];

    float px = pcx + pr * ct;
    float py = pcy + pr * st;
    float ix = icx + ir * ct;
    float iy = icy + ir * st;

    float rad = (float)row / (float)(PH - 1);
    float xg = (1.0f - rad) * px + rad * ix;
    float yg = (1.0f - rad) * py + rad * iy;

    float x = fminf(fmaxf(xg, 0.0f), (float)(W - 1));
    float y = fminf(fmaxf(yg, 0.0f), (float)(H - 1));

    float xn = x / (float)(W - 1) * 2.0f - 1.0f;
    float yn = y / (float)(H - 1) * 2.0f - 1.0f;
    float gx = ((xn + 1.0f) * 0.5f * (float)W - 0.5f) / (float)(W - 1) * 2.0f - 1.0f;
    float gy = ((yn + 1.0f) * 0.5f * (float)H - 0.5f) / (float)(H - 1) * 2.0f - 1.0f;
    float sx = ((gx + 1.0f) * (float)W - 1.0f) * 0.5f;
    float sy = ((gy + 1.0f) * (float)H - 1.0f) * 0.5f;

    float x0f = floorf(sx), y0f = floorf(sy);
    float wx = sx - x0f, wy = sy - y0f;
    int x0 = (int)x0f, y0 = (int)y0f;

    const float* im = img + (size_t)b * H * W;

    float v00 = 0.f, v01 = 0.f, v10 = 0.f, v11 = 0.f;
    bool xv0 = (x0 >= 0) && (x0 < W);
    bool xv1 = (x0+1 >= 0) && (x0+1 < W);
    bool yv0 = (y0 >= 0) && (y0 < H);
    bool yv1 = (y0+1 >= 0) && (y0+1 < H);
    int x0c = min(max(x0, 0), W-1), x1c = min(max(x0+1, 0), W-1);
    int y0c = min(max(y0, 0), H-1), y1c = min(max(y0+1, 0), H-1);
    if (xv0 && yv0) v00 = im[y0c*W + x0c] * 255.0f;
    if (xv1 && yv0) v01 = im[y0c*W + x1c] * 255.0f;
    if (xv0 && yv1) v10 = im[y1c*W + x0c] * 255.0f;
    if (xv1 && yv1) v11 = im[y1c*W + x1c] * 255.0f;

    float v = v00*(1.0f-wx)*(1.0f-wy) + v01*wx*(1.0f-wy)
            + v10*(1.0f-wx)*wy        + v11*wx*wy;
    polar[idx] = v;
}

// ===========================================================================
// Kernel 2: conv as fp16 implicit GEMM, SINGLE term (A fp16, B fp16).
// Rounding errors average across the 225-tap reduction (codes ~3e-4).
// Block (b, y-strip of 8), 256 thr / 8 warps, 4 MMA per filter row.
// ===========================================================================
__global__ __launch_bounds__(256, 4)
void conv_mma_kernel(const float* __restrict__ polar,
                     const float* __restrict__ filt,
                     float* __restrict__ codes) {
    extern __shared__ uint32_t cs[];
    uint32_t* aE  = cs;
    uint32_t* aO  = cs + ATILE_U32;
    uint32_t* Bs  = cs + 2*ATILE_U32;

    int b  = blockIdx.x;
    int y0 = blockIdx.y * 8;
    int tid = threadIdx.x, wid = tid >> 5, lane = tid & 31;

    // B fill: Bs[i][kp][n] = fp16x2 (k=2kp,2kp+1), n->o flip baked in
    for (int e = tid; e < 960; e += 256) {
        int i = e >> 6, kp = (e >> 3) & 7, n = e & 7;
        int k0 = 2*kp, k1 = 2*kp + 1;
        float w0 = (k0 < FS && n < NF) ? filt[(i*FS + k0)*NF + (6 - n)] : 0.f;
        float w1 = (k1 < FS && n < NF) ? filt[(i*FS + k1)*NF + (6 - n)] : 0.f;
        __half h0 = __float2half(w0);
        __half h1 = __float2half(w1);
        Bs[e] = ((uint32_t)__half_as_ushort(h1) << 16) | __half_as_ushort(h0);
    }
    // A fill: 22 rows x 529 cols (wrap), even + odd-shift fp16 copies
    const float* pb = polar + (size_t)b * PH * PW;
    __half* aEh = (__half*)aE;
    __half* aOh = (__half*)aO;
    for (int e = tid; e < AROWS * 529; e += 256) {
        int r = e / 529, c = e % 529;
        int gy = (y0 - RAD + r) & (PH - 1);
        int gx = (c - RAD) & (PW - 1);
        __half h = __float2half(pb[gy*PW + gx]);
        aEh[r*SAB + c] = h;
        if (c > 0) aOh[r*SAB + c - 1] = h;
    }
    __syncthreads();

    int yl = wid;
    int pe = (lane >> 2) & 1;
    int lofs = ((lane >> 2) >> 1) + (lane & 3);
    const uint32_t* pAbase = pe ? aO : aE;
    int bi0 = (lane & 3)*8 + (lane >> 2);

    for (int xt = 0; xt < 8; xt++) {
        int x0 = xt * 64;
        int xofs = x0 >> 1;
        float acc[4][4];
        #pragma unroll
        for (int mf = 0; mf < 4; mf++)
            acc[mf][0] = acc[mf][1] = acc[mf][2] = acc[mf][3] = 0.f;

        #pragma unroll 1
        for (int i = 0; i < FS; i++) {
            const uint32_t* pA = pAbase + (yl + i)*SAU + xofs + lofs;
            uint32_t va[9];
            #pragma unroll
            for (int s = 0; s < 9; s++) va[s] = pA[4*s];
            uint32_t b0 = Bs[i*64 + bi0];
            uint32_t b1 = Bs[i*64 + bi0 + 32];
            #pragma unroll
            for (int mf = 0; mf < 4; mf++) {
                uint32_t a[4] = {va[2*mf], va[2*mf+1], va[2*mf+1], va[2*mf+2]};
                mma_f16(acc[mf], a, b0, b1);
            }
        }

        int y = y0 + yl;
        int n0 = 2*(lane & 3);
        #pragma unroll
        for (int mf = 0; mf < 4; mf++) {
            int xa = x0 + mf*16 + (lane >> 2);
            #pragma unroll
            for (int q = 0; q < 4; q++) {
                int o = n0 + (q & 1);
                if (o >= NF) continue;
                int x = xa + (q >> 1)*8;
                float v = acc[mf][q];
                size_t off = (((size_t)(b*NF + o))*PH + y)*PW + x;
                codes[off] = v;
                g_h[off] = __float2half(v * FSCALE);
            }
        }
    }
}

// ===========================================================================
// Kernel 3: gram via mma.sync fp16 single-term, 16 warps, 4-stage ring,
// one sync per iter. (unchanged R9)
// ===========================================================================
__device__ __forceinline__ void gram_load_stage(uint32_t sbase, int stage, int it,
                                                int ti, int tj, int ksp, int tid, int nm) {
    uint32_t st = sbase + stage * STAGE_BY;
    size_t kbyte = ((size_t)ksp * GKCHUNK + (size_t)it * KB) * 2;
    int row = tid >> 2, k8 = tid & 3;
    uint32_t doff = (uint32_t)(row * (TSTRIDE*2) + k8 * 16);
    #pragma unroll
    for (int m = 0; m < 2; m++) {
        if (m >= nm) break;
        int grow = ((m == 0) ? ti : tj) * 128 + row;
        uint32_t dst = st + m * TILE_BY + doff;
        const char* src = (const char*)g_h + (size_t)min(grow, N_ROWS-1) * (K_TOT*2) + kbyte + k8 * 16;
        if (grow < N_ROWS) cp16(dst, src);
        else               cp16z(dst, src);
    }
}

__global__ __launch_bounds__(512, 2)
void gram_mma_kernel() {
    extern __shared__ char dsm[];
    uint32_t sbase = smem_u32(dsm);

    int pair = blockIdx.x;
    int ksp  = blockIdx.y;
    int ti = 0, rem = pair, cnt = GT;
    while (rem >= cnt) { rem -= cnt; ti++; cnt--; }
    int tj = ti + rem;
    bool diag = (ti == tj);
    int nm = diag ? 1 : 2;

    int tid  = threadIdx.x;
    int wid  = tid >> 5, lane = tid & 31;
    int warp_m = wid & 3;
    int warp_n = wid >> 2;

    float acc[2][4][4];
    #pragma unroll
    for (int mi = 0; mi < 2; mi++)
        #pragma unroll
        for (int ni = 0; ni < 4; ni++)
            #pragma unroll
            for (int q = 0; q < 4; q++) acc[mi][ni][q] = 0.f;

    uint32_t a_off = (uint32_t)((warp_m*32 + (lane & 15)) * (TSTRIDE*2) + ((lane >> 4) & 1) * 16);
    uint32_t b_off = (uint32_t)((warp_n*32 + (lane & 15)) * (TSTRIDE*2) + ((lane >> 4) & 1) * 16);

    #pragma unroll
    for (int p = 0; p < 3; p++) {
        gram_load_stage(sbase, p, p, ti, tj, ksp, tid, nm);
        cp_commit();
    }

    for (int it = 0; it < KITERS; it++) {
        cp_wait2();
        __syncthreads();

        int nx = it + 3;
        if (nx < KITERS) gram_load_stage(sbase, nx & 3, nx, ti, tj, ksp, tid, nm);
        cp_commit();

        uint32_t st = sbase + (it & 3) * STAGE_BY;
        uint32_t aB = st;
        uint32_t bB = diag ? st : st + TILE_BY;

        #pragma unroll
        for (int k16 = 0; k16 < 2; k16++) {
            uint32_t kadd = (uint32_t)(k16 * 32);
            uint32_t af[2][4], bf[2][4];
            #pragma unroll
            for (int mi = 0; mi < 2; mi++)
                ldm_x4(af[mi], aB + a_off + kadd + mi*16*(TSTRIDE*2));
            #pragma unroll
            for (int n2 = 0; n2 < 2; n2++)
                ldm_x4(bf[n2], bB + b_off + kadd + n2*16*(TSTRIDE*2));
            #pragma unroll
            for (int mi = 0; mi < 2; mi++)
                #pragma unroll
                for (int ni = 0; ni < 4; ni++) {
                    int n2 = ni >> 1, sel = ni & 1;
                    mma_f16(acc[mi][ni], af[mi], bf[n2][sel], bf[n2][sel+2]);
                }
        }
    }

    float* dst = &g_gpart[pair][ksp][0];
    int r0 = warp_m * 32;
    int c0 = warp_n * 32;
    #pragma unroll
    for (int mi = 0; mi < 2; mi++) {
        #pragma unroll
        for (int ni = 0; ni < 4; ni++) {
            int row = r0 + mi*16 + (lane >> 2);
            int col = c0 + ni*8 + (lane & 3) * 2;
            *(float2*)&dst[row * 128 + col]       = make_float2(acc[mi][ni][0], acc[mi][ni][1]);
            *(float2*)&dst[(row + 8) * 128 + col] = make_float2(acc[mi][ni][2], acc[mi][ni][3]);
        }
    }
}

// ===========================================================================
// Kernel 4: reduce K-splits (float4 per thread), scale, symmetric write
// ===========================================================================
__global__ void gram_reduce_kernel(float* __restrict__ gram) {
    int idx = blockIdx.x * blockDim.x + threadIdx.x;      // GPAIRS*4096
    if (idx >= GPAIRS * 4096) return;
    int pair = idx >> 12;
    int e4   = (idx & 4095) * 4;
    int ii = e4 >> 7, jj = e4 & 127;

    int ti = 0, rem = pair, cnt = GT;
    while (rem >= cnt) { rem -= cnt; ti++; cnt--; }
    int tj = ti + rem;

    int gi = ti * 128 + ii;
    if (gi >= N_ROWS) return;
    int gj0 = tj * 128 + jj;

    float4 s = make_float4(0.f, 0.f, 0.f, 0.f);
    #pragma unroll
    for (int k = 0; k < GKSPLIT; k++) {
        float4 v = *(const float4*)&g_gpart[pair][k][e4];
        s.x += v.x; s.y += v.y; s.z += v.z; s.w += v.w;
    }
    s.x *= GRAM_SCALE; s.y *= GRAM_SCALE; s.z *= GRAM_SCALE; s.w *= GRAM_SCALE;

    float vs[4] = {s.x, s.y, s.z, s.w};
    int nvalid = min(4, N_ROWS - gj0);
    if (nvalid == 4) {
        *(float4*)&gram[gi * N_ROWS + gj0] = s;
    } else {
        for (int q = 0; q < nvalid; q++) gram[gi * N_ROWS + gj0 + q] = vs[q];
    }
    #pragma unroll
    for (int q = 0; q < 4; q++) {
        int gj = gj0 + q;
        if (gj < N_ROWS) gram[gj * N_ROWS + gi] = vs[q];
    }
}

// ===========================================================================
extern "C" void kernel_launch(void* const* d_in, const int* in_sizes, int n_in,
                              void* d_out, int out_size) {
    const float* image = (const float*)d_in[0];
    const float* pupil = (const float*)d_in[1];
    const float* iris  = (const float*)d_in[2];
    const float* filt  = (const float*)d_in[3];

    float* out   = (float*)d_out;
    float* codes = out + CODES_OFF;
    float* gram  = out + GRAM_OFF;
    float* polar = out + POLAR_OFF;

    cudaFuncSetAttribute(conv_mma_kernel,
                         cudaFuncAttributeMaxDynamicSharedMemorySize, CONV_SMEM);
    cudaFuncSetAttribute(gram_mma_kernel,
                         cudaFuncAttributeMaxDynamicSharedMemorySize, GSMEM);

    polar_kernel<<<(B * PH * PW) / 256, 256>>>(image, pupil, iris, polar);
    conv_mma_kernel<<<dim3(B, PH/8), 256, CONV_SMEM>>>(polar, filt, codes);
    gram_mma_kernel<<<dim3(GPAIRS, GKSPLIT), 512, GSMEM>>>();
    gram_reduce_kernel<<<(GPAIRS * 4096 + 255) / 256, 256>>>(gram);
}

// round 11
// speedup vs baseline: 2.6625x; 1.0342x over previous
#include <cuda_runtime.h>
#include <cuda_fp16.h>
#include <cstdint>

#define B   64
#define H   480
#define W   640
#define PH  64
#define PW  512
#define FS  15
#define NF  7
#define RAD 7

#define K_TOT   (PH*PW)          // 32768
#define N_ROWS  (B*NF)           // 448

#define CODES_OFF 0
#define GRAM_OFF  (B*NF*PH*PW)                // 14680064
#define POLAR_OFF (GRAM_OFF + N_ROWS*N_ROWS)  // 14880768

#define FSCALE      0.0625f                   // feats stored * 1/16
#define GRAM_SCALE  (256.0f / 14680064.0f)    // undo FSCALE^2 and normalize

// ---- gram tiling ----
// 1024 total k-iterations (KB=32 each) split unevenly over 59 CTAs per pair:
// splits 0..20 do 18 iters, 21..58 do 17  (21*18 + 38*17 = 1024).
// Grid = 10 pairs x 59 = 590 CTAs = exactly 2 waves at 2 CTAs/SM on 148 SMs.
#define GT       4
#define GPAIRS   10
#define GKSPLIT  59
#define KB       32

#define TSTRIDE  40                 // fp16 per smem row (80B)
#define TILE_BY  (128*TSTRIDE*2)    // 10240 B
#define STAGE_BY (2*TILE_BY)        // 20480 B (A|B, single term)
#define NSTAGE   4
#define GSMEM    (NSTAGE*STAGE_BY)  // 81920 B -> 2 CTAs/SM

// ---- conv (fp16 implicit GEMM, single term) ----
#define SAB 536                     // fp16 stride per A row
#define SAU 268                     // u32 stride
#define AROWS 22                    // 8 + 14
#define ATILE_U32 (AROWS*SAU)       // 5896
#define CONV_SMEM ((2*ATILE_U32 + 960)*4)     // 51008 B -> 4 CTAs/SM

// scratch (device-code references ONLY — host-side symbol use is a silent
// ATS write to host BSS on GB300)
__device__ __half g_h[(size_t)N_ROWS * K_TOT];
__device__ float g_gpart[GPAIRS][GKSPLIT][128*128];

// ===========================================================================
// helpers
// ===========================================================================
__device__ __forceinline__ uint32_t smem_u32(const void* p) {
    uint32_t a;
    asm("{ .reg .u64 t; cvta.to.shared.u64 t, %1; cvt.u32.u64 %0, t; }" : "=r"(a) : "l"(p));
    return a;
}

__device__ __forceinline__ void cp16(uint32_t dst, const void* src) {
    asm volatile("cp.async.ca.shared.global [%0], [%1], 16;" :: "r"(dst), "l"(src));
}
__device__ __forceinline__ void cp16z(uint32_t dst, const void* src) {
    asm volatile("cp.async.ca.shared.global [%0], [%1], 16, 0;" :: "r"(dst), "l"(src));
}
__device__ __forceinline__ void cp_commit() { asm volatile("cp.async.commit_group;" ::: "memory"); }
__device__ __forceinline__ void cp_wait2()  { asm volatile("cp.async.wait_group 2;" ::: "memory"); }

__device__ __forceinline__ void ldm_x4(uint32_t* r, uint32_t addr) {
    asm volatile("ldmatrix.sync.aligned.m8n8.x4.shared.b16 {%0,%1,%2,%3}, [%4];"
        : "=r"(r[0]), "=r"(r[1]), "=r"(r[2]), "=r"(r[3]) : "r"(addr));
}
__device__ __forceinline__ void mma_f16(float* c, const uint32_t* a, uint32_t b0, uint32_t b1) {
    asm volatile("mma.sync.aligned.m16n8k16.row.col.f32.f16.f16.f32 "
        "{%0,%1,%2,%3}, {%4,%5,%6,%7}, {%8,%9}, {%0,%1,%2,%3};"
        : "+f"(c[0]), "+f"(c[1]), "+f"(c[2]), "+f"(c[3])
        : "r"(a[0]), "r"(a[1]), "r"(a[2]), "r"(a[3]), "r"(b0), "r"(b1));
}

// ===========================================================================
// Kernel 1: polar bilinear resample
// ===========================================================================
__global__ void polar_kernel(const float* __restrict__ img,
                             const float* __restrict__ pupil,
                             const float* __restrict__ iris,
                             float* __restrict__ polar) {
    int idx = blockIdx.x * blockDim.x + threadIdx.x;
    if (idx >= B * PH * PW) return;
    int col = idx % PW;
    int row = (idx / PW) % PH;
    int b   = idx / (PH * PW);

    float theta = 6.283185307179586f * (float)(col + 1) * (1.0f / (float)PW);
    float ct = cosf(theta), st = sinf(theta);

    float pcx = pupil[b*3+0], pcy = pupil[b*3+1], pr = pupil[b*3+2];
    float icx = iris [b*3+0], icy = iris [b*3+1], ir = iris [b*3+2];

    float px = pcx + pr * ct;
    float py = pcy + pr * st;
    float ix = icx + ir * ct;
    float iy = icy + ir * st;

    float rad = (float)row / (float)(PH - 1);
    float xg = (1.0f - rad) * px + rad * ix;
    float yg = (1.0f - rad) * py + rad * iy;

    float x = fminf(fmaxf(xg, 0.0f), (float)(W - 1));
    float y = fminf(fmaxf(yg, 0.0f), (float)(H - 1));

    float xn = x / (float)(W - 1) * 2.0f - 1.0f;
    float yn = y / (float)(H - 1) * 2.0f - 1.0f;
    float gx = ((xn + 1.0f) * 0.5f * (float)W - 0.5f) / (float)(W - 1) * 2.0f - 1.0f;
    float gy = ((yn + 1.0f) * 0.5f * (float)H - 0.5f) / (float)(H - 1) * 2.0f - 1.0f;
    float sx = ((gx + 1.0f) * (float)W - 1.0f) * 0.5f;
    float sy = ((gy + 1.0f) * (float)H - 1.0f) * 0.5f;

    float x0f = floorf(sx), y0f = floorf(sy);
    float wx = sx - x0f, wy = sy - y0f;
    int x0 = (int)x0f, y0 = (int)y0f;

    const float* im = img + (size_t)b * H * W;

    float v00 = 0.f, v01 = 0.f, v10 = 0.f, v11 = 0.f;
    bool xv0 = (x0 >= 0) && (x0 < W);
    bool xv1 = (x0+1 >= 0) && (x0+1 < W);
    bool yv0 = (y0 >= 0) && (y0 < H);
    bool yv1 = (y0+1 >= 0) && (y0+1 < H);
    int x0c = min(max(x0, 0), W-1), x1c = min(max(x0+1, 0), W-1);
    int y0c = min(max(y0, 0), H-1), y1c = min(max(y0+1, 0), H-1);
    if (xv0 && yv0) v00 = im[y0c*W + x0c] * 255.0f;
    if (xv1 && yv0) v01 = im[y0c*W + x1c] * 255.0f;
    if (xv0 && yv1) v10 = im[y1c*W + x0c] * 255.0f;
    if (xv1 && yv1) v11 = im[y1c*W + x1c] * 255.0f;

    float v = v00*(1.0f-wx)*(1.0f-wy) + v01*wx*(1.0f-wy)
            + v10*(1.0f-wx)*wy        + v11*wx*wy;
    polar[idx] = v;
}

// ===========================================================================
// Kernel 2: conv as fp16 implicit GEMM, SINGLE term. (unchanged R10)
// ===========================================================================
__global__ __launch_bounds__(256, 4)
void conv_mma_kernel(const float* __restrict__ polar,
                     const float* __restrict__ filt,
                     float* __restrict__ codes) {
    extern __shared__ uint32_t cs[];
    uint32_t* aE  = cs;
    uint32_t* aO  = cs + ATILE_U32;
    uint32_t* Bs  = cs + 2*ATILE_U32;

    int b  = blockIdx.x;
    int y0 = blockIdx.y * 8;
    int tid = threadIdx.x, wid = tid >> 5, lane = tid & 31;

    for (int e = tid; e < 960; e += 256) {
        int i = e >> 6, kp = (e >> 3) & 7, n = e & 7;
        int k0 = 2*kp, k1 = 2*kp + 1;
        float w0 = (k0 < FS && n < NF) ? filt[(i*FS + k0)*NF + (6 - n)] : 0.f;
        float w1 = (k1 < FS && n < NF) ? filt[(i*FS + k1)*NF + (6 - n)] : 0.f;
        __half h0 = __float2half(w0);
        __half h1 = __float2half(w1);
        Bs[e] = ((uint32_t)__half_as_ushort(h1) << 16) | __half_as_ushort(h0);
    }
    const float* pb = polar + (size_t)b * PH * PW;
    __half* aEh = (__half*)aE;
    __half* aOh = (__half*)aO;
    for (int e = tid; e < AROWS * 529; e += 256) {
        int r = e / 529, c = e % 529;
        int gy = (y0 - RAD + r) & (PH - 1);
        int gx = (c - RAD) & (PW - 1);
        __half h = __float2half(pb[gy*PW + gx]);
        aEh[r*SAB + c] = h;
        if (c > 0) aOh[r*SAB + c - 1] = h;
    }
    __syncthreads();

    int yl = wid;
    int pe = (lane >> 2) & 1;
    int lofs = ((lane >> 2) >> 1) + (lane & 3);
    const uint32_t* pAbase = pe ? aO : aE;
    int bi0 = (lane & 3)*8 + (lane >> 2);

    for (int xt = 0; xt < 8; xt++) {
        int x0 = xt * 64;
        int xofs = x0 >> 1;
        float acc[4][4];
        #pragma unroll
        for (int mf = 0; mf < 4; mf++)
            acc[mf][0] = acc[mf][1] = acc[mf][2] = acc[mf][3] = 0.f;

        #pragma unroll 1
        for (int i = 0; i < FS; i++) {
            const uint32_t* pA = pAbase + (yl + i)*SAU + xofs + lofs;
            uint32_t va[9];
            #pragma unroll
            for (int s = 0; s < 9; s++) va[s] = pA[4*s];
            uint32_t b0 = Bs[i*64 + bi0];
            uint32_t b1 = Bs[i*64 + bi0 + 32];
            #pragma unroll
            for (int mf = 0; mf < 4; mf++) {
                uint32_t a[4] = {va[2*mf], va[2*mf+1], va[2*mf+1], va[2*mf+2]};
                mma_f16(acc[mf], a, b0, b1);
            }
        }

        int y = y0 + yl;
        int n0 = 2*(lane & 3);
        #pragma unroll
        for (int mf = 0; mf < 4; mf++) {
            int xa = x0 + mf*16 + (lane >> 2);
            #pragma unroll
            for (int q = 0; q < 4; q++) {
                int o = n0 + (q & 1);
                if (o >= NF) continue;
                int x = xa + (q >> 1)*8;
                float v = acc[mf][q];
                size_t off = (((size_t)(b*NF + o))*PH + y)*PW + x;
                codes[off] = v;
                g_h[off] = __float2half(v * FSCALE);
            }
        }
    }
}

// ===========================================================================
// Kernel 3: gram via mma.sync fp16 single-term, 16 warps, 4-stage ring.
// Uneven k-split: split s does 18 iters (s<21) else 17; start = 17s+min(s,21).
// ===========================================================================
__device__ __forceinline__ void gram_load_stage(uint32_t sbase, int stage, int kit,
                                                int ti, int tj, int tid, int nm) {
    uint32_t st = sbase + stage * STAGE_BY;
    size_t kbyte = (size_t)kit * (KB * 2);
    int row = tid >> 2, k8 = tid & 3;
    uint32_t doff = (uint32_t)(row * (TSTRIDE*2) + k8 * 16);
    #pragma unroll
    for (int m = 0; m < 2; m++) {
        if (m >= nm) break;
        int grow = ((m == 0) ? ti : tj) * 128 + row;
        uint32_t dst = st + m * TILE_BY + doff;
        const char* src = (const char*)g_h + (size_t)min(grow, N_ROWS-1) * (K_TOT*2) + kbyte + k8 * 16;
        if (grow < N_ROWS) cp16(dst, src);
        else               cp16z(dst, src);
    }
}

__global__ __launch_bounds__(512, 2)
void gram_mma_kernel() {
    extern __shared__ char dsm[];
    uint32_t sbase = smem_u32(dsm);

    int pair = blockIdx.x;
    int ksp  = blockIdx.y;
    int ti = 0, rem = pair, cnt = GT;
    while (rem >= cnt) { rem -= cnt; ti++; cnt--; }
    int tj = ti + rem;
    bool diag = (ti == tj);
    int nm = diag ? 1 : 2;

    int kstart = 17*ksp + min(ksp, 21);
    int kiters = 17 + (ksp < 21 ? 1 : 0);

    int tid  = threadIdx.x;
    int wid  = tid >> 5, lane = tid & 31;
    int warp_m = wid & 3;
    int warp_n = wid >> 2;

    float acc[2][4][4];
    #pragma unroll
    for (int mi = 0; mi < 2; mi++)
        #pragma unroll
        for (int ni = 0; ni < 4; ni++)
            #pragma unroll
            for (int q = 0; q < 4; q++) acc[mi][ni][q] = 0.f;

    uint32_t a_off = (uint32_t)((warp_m*32 + (lane & 15)) * (TSTRIDE*2) + ((lane >> 4) & 1) * 16);
    uint32_t b_off = (uint32_t)((warp_n*32 + (lane & 15)) * (TSTRIDE*2) + ((lane >> 4) & 1) * 16);

    #pragma unroll
    for (int p = 0; p < 3; p++) {
        gram_load_stage(sbase, p, kstart + p, ti, tj, tid, nm);
        cp_commit();
    }

    for (int it = 0; it < kiters; it++) {
        cp_wait2();
        __syncthreads();

        int nx = it + 3;
        if (nx < kiters) gram_load_stage(sbase, nx & 3, kstart + nx, ti, tj, tid, nm);
        cp_commit();

        uint32_t st = sbase + (it & 3) * STAGE_BY;
        uint32_t aB = st;
        uint32_t bB = diag ? st : st + TILE_BY;

        #pragma unroll
        for (int k16 = 0; k16 < 2; k16++) {
            uint32_t kadd = (uint32_t)(k16 * 32);
            uint32_t af[2][4], bf[2][4];
            #pragma unroll
            for (int mi = 0; mi < 2; mi++)
                ldm_x4(af[mi], aB + a_off + kadd + mi*16*(TSTRIDE*2));
            #pragma unroll
            for (int n2 = 0; n2 < 2; n2++)
                ldm_x4(bf[n2], bB + b_off + kadd + n2*16*(TSTRIDE*2));
            #pragma unroll
            for (int mi = 0; mi < 2; mi++)
                #pragma unroll
                for (int ni = 0; ni < 4; ni++) {
                    int n2 = ni >> 1, sel = ni & 1;
                    mma_f16(acc[mi][ni], af[mi], bf[n2][sel], bf[n2][sel+2]);
                }
        }
    }

    float* dst = &g_gpart[pair][ksp][0];
    int r0 = warp_m * 32;
    int c0 = warp_n * 32;
    #pragma unroll
    for (int mi = 0; mi < 2; mi++) {
        #pragma unroll
        for (int ni = 0; ni < 4; ni++) {
            int row = r0 + mi*16 + (lane >> 2);
            int col = c0 + ni*8 + (lane & 3) * 2;
            *(float2*)&dst[row * 128 + col]       = make_float2(acc[mi][ni][0], acc[mi][ni][1]);
            *(float2*)&dst[(row + 8) * 128 + col] = make_float2(acc[mi][ni][2], acc[mi][ni][3]);
        }
    }
}

// ===========================================================================
// Kernel 4: reduce 59 K-splits, 4 threads per float4 element (deterministic
// fixed-order partial sums + fixed-order smem tree), scale, symmetric write.
// ===========================================================================
__global__ void gram_reduce_kernel(float* __restrict__ gram) {
    __shared__ float4 sm[64][4];
    int bid  = blockIdx.x;            // 0..639
    int pair = bid >> 6;
    int eblk = bid & 63;
    int tid  = threadIdx.x;
    int el   = tid >> 2;              // 0..63
    int q    = tid & 3;

    int e4 = (eblk * 64 + el) * 4;    // float index within 16384
    int kstart = q * 15;
    int kcnt   = (q < 3) ? 15 : 14;   // 15+15+15+14 = 59

    const float* base = &g_gpart[pair][0][0];
    float4 s = make_float4(0.f, 0.f, 0.f, 0.f);
    for (int k = 0; k < kcnt; k++) {
        float4 v = *(const float4*)(base + (size_t)(kstart + k) * 16384 + e4);
        s.x += v.x; s.y += v.y; s.z += v.z; s.w += v.w;
    }
    sm[el][q] = s;
    __syncthreads();

    if (q == 0) {
        float4 a = sm[el][0], b = sm[el][1], c = sm[el][2], d = sm[el][3];
        float4 t;
        t.x = (((a.x + b.x) + c.x) + d.x) * GRAM_SCALE;
        t.y = (((a.y + b.y) + c.y) + d.y) * GRAM_SCALE;
        t.z = (((a.z + b.z) + c.z) + d.z) * GRAM_SCALE;
        t.w = (((a.w + b.w) + c.w) + d.w) * GRAM_SCALE;

        int ii = e4 >> 7, jj = e4 & 127;
        int ti = 0, rem = pair, cnt = GT;
        while (rem >= cnt) { rem -= cnt; ti++; cnt--; }
        int tj = ti + rem;

        int gi  = ti * 128 + ii;
        int gj0 = tj * 128 + jj;
        if (gi < N_ROWS) {
            float vs[4] = {t.x, t.y, t.z, t.w};
            int nvalid = min(4, N_ROWS - gj0);
            if (nvalid == 4) {
                *(float4*)&gram[gi * N_ROWS + gj0] = t;
            } else {
                for (int p = 0; p < nvalid; p++) gram[gi * N_ROWS + gj0 + p] = vs[p];
            }
            #pragma unroll
            for (int p = 0; p < 4; p++) {
                int gj = gj0 + p;
                if (gj < N_ROWS) gram[gj * N_ROWS + gi] = vs[p];
            }
        }
    }
}

// ===========================================================================
extern "C" void kernel_launch(void* const* d_in, const int* in_sizes, int n_in,
                              void* d_out, int out_size) {
    const float* image = (const float*)d_in[0];
    const float* pupil = (const float*)d_in[1];
    const float* iris  = (const float*)d_in[2];
    const float* filt  = (const float*)d_in[3];

    float* out   = (float*)d_out;
    float* codes = out + CODES_OFF;
    float* gram  = out + GRAM_OFF;
    float* polar = out + POLAR_OFF;

    cudaFuncSetAttribute(conv_mma_kernel,
                         cudaFuncAttributeMaxDynamicSharedMemorySize, CONV_SMEM);
    cudaFuncSetAttribute(gram_mma_kernel,
                         cudaFuncAttributeMaxDynamicSharedMemorySize, GSMEM);

    polar_kernel<<<(B * PH * PW) / 256, 256>>>(image, pupil, iris, polar);
    conv_mma_kernel<<<dim3(B, PH/8), 256, CONV_SMEM>>>(polar, filt, codes);
    gram_mma_kernel<<<dim3(GPAIRS, GKSPLIT), 512, GSMEM>>>();
    gram_reduce_kernel<<<GPAIRS * 64, 256>>>(gram);
}